// round 9
// baseline (speedup 1.0000x reference)
#include <cuda_runtime.h>
#include <cuda_bf16.h>
#include <math.h>
#include <stdint.h>

#define BATCH 65536
#define NQ    256

typedef __nv_bfloat16  bf16;
typedef __nv_bfloat162 bf162;

// ======================= scratch (device globals) =======================
__device__ __align__(256) float g_lin  [8 * NQ];
__device__ __align__(256) float g_bfold[2 * NQ];

__device__ __align__(256) bf16 g_xh [BATCH * NQ];
__device__ __align__(256) bf16 g_xl [BATCH * NQ];
__device__ __align__(256) bf16 g_Ah [BATCH * NQ];
__device__ __align__(256) bf16 g_Al [BATCH * NQ];
__device__ __align__(256) bf16 g_Bh2[BATCH * NQ];
__device__ __align__(256) bf16 g_Bl2[BATCH * NQ];
__device__ __align__(256) bf16 g_h0h[BATCH * 768];
__device__ __align__(256) bf16 g_h0l[BATCH * 768];
__device__ __align__(256) bf16 g_hh [BATCH * 768];
__device__ __align__(256) bf16 g_hl [BATCH * 768];
__device__ __align__(256) bf16 g_t2h[BATCH * NQ];
__device__ __align__(256) bf16 g_t2l[BATCH * NQ];
__device__ __align__(256) bf16 g_t3h[BATCH * NQ];
__device__ __align__(256) bf16 g_t3l[BATCH * NQ];

#define WTOT 3276800
__device__ __align__(256) bf16 g_wh[WTOT];
__device__ __align__(256) bf16 g_wl[WTOT];

// ======================= helpers =======================
__device__ __forceinline__ uint32_t smem_u32(const void* p) {
    uint32_t a;
    asm("{ .reg .u64 t; cvta.to.shared.u64 t, %1; cvt.u32.u64 %0, t; }" : "=r"(a) : "l"(p));
    return a;
}

#define CP_ASYNC16(dst, src) \
    asm volatile("cp.async.cg.shared.global [%0], [%1], 16;" :: "r"(dst), "l"(src) : "memory")
#define CP_COMMIT() asm volatile("cp.async.commit_group;" ::: "memory")
#define CP_WAIT1()  asm volatile("cp.async.wait_group 1;" ::: "memory")

#define LDSM4(r0, r1, r2, r3, addr) \
    asm volatile("ldmatrix.sync.aligned.m8n8.x4.shared.b16 {%0,%1,%2,%3}, [%4];" \
        : "=r"(r0), "=r"(r1), "=r"(r2), "=r"(r3) : "r"(addr))

__device__ __forceinline__ void mma_bf16(float* d, const uint32_t* a, const uint32_t* b) {
    asm volatile(
        "mma.sync.aligned.m16n8k16.row.col.f32.bf16.bf16.f32 "
        "{%0,%1,%2,%3}, {%4,%5,%6,%7}, {%8,%9}, {%0,%1,%2,%3};"
        : "+f"(d[0]), "+f"(d[1]), "+f"(d[2]), "+f"(d[3])
        : "r"(a[0]), "r"(a[1]), "r"(a[2]), "r"(a[3]), "r"(b[0]), "r"(b[1]));
}

__device__ __forceinline__ bf162 split_hi2(float a, float b, bf162& lo) {
    bf16 ha = __float2bfloat16(a);
    bf16 hb = __float2bfloat16(b);
    bf16 la = __float2bfloat16(a - __bfloat162float(ha));
    bf16 lb = __float2bfloat16(b - __bfloat162float(hb));
    lo = __halves2bfloat162(la, lb);
    return __halves2bfloat162(ha, hb);
}
__device__ __forceinline__ float join2(bf16 h, bf16 l) {
    return __bfloat162float(h) + __bfloat162float(l);
}

// ======================= smem layout (tile 64 M x 256 N, k-chunk 32) ====
#define MAT_A_BYTES 5120      // 64 rows * 80B pitch
#define MAT_B_BYTES 20480     // 256 rows * 80B pitch
#define ST_AH 0
#define ST_AL 5120
#define ST_BH 10240
#define ST_BL 30720
#define STAGE_BYTES 51200
#define STAGES 3
#define SMEM_BYTES (STAGES * STAGE_BYTES)

// ======================= mma.sync GEMM =======================
// C[64-row tile x 256-col tile] = epi(A @ W^T + bias), optional fused mix.
// A hi/lo bf16 [B x K]; W hi/lo bf16 [N x K] (k contiguous).
// EPI: 0 bias, 1 silu, 2 tanh, 3 gate+entangle, 4 nl-residual
// MIX: fuse alpha-mix with res + row L2-normalize + tanh
// OUTF32: mix writes f32 (d_out) instead of hi/lo
template <int EPI, int MIX, int OUTF32>
__global__ __launch_bounds__(256, 1) void gemm_mma(
    const bf16* __restrict__ Ah, const bf16* __restrict__ Al,
    const bf16* __restrict__ Bh, const bf16* __restrict__ Bl,
    const float* __restrict__ bias,
    bf16* __restrict__ outh, bf16* __restrict__ outl, float* __restrict__ outf,
    const bf16* __restrict__ auxh, const bf16* __restrict__ auxl,
    const bf16* __restrict__ resh, const bf16* __restrict__ resl,
    const float* __restrict__ gp, const float* __restrict__ lin,
    float alpha, int K, int N)
{
    extern __shared__ char sm[];
    const uint32_t smem_base = smem_u32(sm);

    const int tid    = threadIdx.x;
    const int wid    = tid >> 5;
    const int lane   = tid & 31;
    const int warp_m = wid & 1;        // 2 warps over M: 32 rows each
    const int warp_n = wid >> 1;       // 4 warps over N: 64 cols each
    const int m0     = blockIdx.y * 64;
    const int n0     = blockIdx.x * 256;

    float acc[2][8][4];
#pragma unroll
    for (int a = 0; a < 2; a++)
#pragma unroll
        for (int b = 0; b < 8; b++)
#pragma unroll
            for (int c = 0; c < 4; c++) acc[a][b][c] = 0.f;

    const int nk = K >> 5;

    auto load_stage = [&](int stage, int kblk) {
        const int k0 = kblk << 5;
        const uint32_t sb = smem_base + stage * STAGE_BYTES;
#pragma unroll
        for (int part = 0; part < 10; part++) {
            int id = tid + part * 256;
            if (id < 512) {
                int mat = id >> 8;          // 0 Ah, 1 Al
                int rem = id & 255;
                int row = rem >> 2, ch = rem & 3;
                const bf16* s = (mat == 0 ? Ah : Al) + (size_t)(m0 + row) * K + k0 + ch * 8;
                CP_ASYNC16(sb + mat * MAT_A_BYTES + row * 80 + ch * 16, s);
            } else {
                int id2 = id - 512;
                int mat = id2 >> 10;        // 0 Bh, 1 Bl
                int rem = id2 & 1023;
                int row = rem >> 2, ch = rem & 3;
                const bf16* s = (mat == 0 ? Bh : Bl) + (size_t)(n0 + row) * K + k0 + ch * 8;
                CP_ASYNC16(sb + ST_BH + mat * MAT_B_BYTES + row * 80 + ch * 16, s);
            }
        }
    };

    load_stage(0, 0); CP_COMMIT();
    load_stage(1, 1); CP_COMMIT();

    const uint32_t a_lane_off = (warp_m * 32 + (lane & 15)) * 80 + ((lane >> 4) << 4);
    const uint32_t b_lane_off = (warp_n * 64 + (lane & 7) + ((lane >> 4) << 3)) * 80
                              + (((lane >> 3) & 1) << 4);

    int st = 0;
    for (int i = 0; i < nk; i++) {
        CP_WAIT1();
        __syncthreads();
        {
            int st2 = st + 2; if (st2 >= 3) st2 -= 3;
            if (i + 2 < nk) load_stage(st2, i + 2);
            CP_COMMIT();
        }
        const uint32_t sb = smem_base + st * STAGE_BYTES;
#pragma unroll
        for (int kk = 0; kk < 2; kk++) {
            const uint32_t koff = kk * 32;
            uint32_t af_h[2][4], af_l[2][4], bf_h[8][2], bf_l[8][2];
#pragma unroll
            for (int mt = 0; mt < 2; mt++) {
                uint32_t off = a_lane_off + mt * 1280 + koff;
                LDSM4(af_h[mt][0], af_h[mt][1], af_h[mt][2], af_h[mt][3], sb + ST_AH + off);
                LDSM4(af_l[mt][0], af_l[mt][1], af_l[mt][2], af_l[mt][3], sb + ST_AL + off);
            }
#pragma unroll
            for (int p = 0; p < 4; p++) {
                uint32_t off = b_lane_off + p * 1280 + koff;
                LDSM4(bf_h[2 * p][0], bf_h[2 * p][1], bf_h[2 * p + 1][0], bf_h[2 * p + 1][1],
                      sb + ST_BH + off);
                LDSM4(bf_l[2 * p][0], bf_l[2 * p][1], bf_l[2 * p + 1][0], bf_l[2 * p + 1][1],
                      sb + ST_BL + off);
            }
#pragma unroll
            for (int mt = 0; mt < 2; mt++)
#pragma unroll
                for (int nt = 0; nt < 8; nt++) {
                    mma_bf16(acc[mt][nt], af_h[mt], bf_h[nt]);
                    mma_bf16(acc[mt][nt], af_l[mt], bf_h[nt]);
                    mma_bf16(acc[mt][nt], af_h[mt], bf_l[nt]);
                }
        }
        st++; if (st >= 3) st = 0;
    }

    // ---------- epilogue ----------
    __syncthreads();                         // allow smem reuse for reduction
    float* red = (float*)sm;                 // [64 rows][4 warp_n]

    const int l4  = lane >> 2;
    const int l2q = lane & 3;
    const int l2  = l2q * 2;
    const float beta = 1.f - alpha;

    // pass 1: apply EPI (+ mix), store back into acc, accumulate row sumsq
#pragma unroll
    for (int mt = 0; mt < 2; mt++) {
#pragma unroll
        for (int h = 0; h < 2; h++) {
            const int mrow = warp_m * 32 + mt * 16 + h * 8 + l4;
            const int m = m0 + mrow;
            float part = 0.f;
#pragma unroll
            for (int nt = 0; nt < 8; nt++) {
                const int n = n0 + warp_n * 64 + nt * 8 + l2;
                float vx = acc[mt][nt][2 * h];
                float vy = acc[mt][nt][2 * h + 1];

                if (EPI != 3) {
                    float2 b2 = *(const float2*)(bias + n);
                    vx += b2.x; vy += b2.y;
                }
                if (EPI == 1) {
                    vx = vx / (1.f + expf(-vx));
                    vy = vy / (1.f + expf(-vy));
                } else if (EPI == 2) {
                    vx = tanhf(vx);
                    vy = tanhf(vy);
                } else if (EPI == 3) {
                    bf162 axh = *(const bf162*)(auxh + (size_t)m * N + n);
                    bf162 axl = *(const bf162*)(auxl + (size_t)m * N + n);
                    float c0 = join2(axh.x, axl.x);
                    float c1 = join2(axh.y, axl.y);
                    float li0 = __ldg(lin + n),     li1 = __ldg(lin + n + 1);
                    float p30 = __ldg(gp + (size_t)n * 6 + 3), p31 = __ldg(gp + (size_t)(n + 1) * 6 + 3);
                    float p40 = __ldg(gp + (size_t)n * 6 + 4), p41 = __ldg(gp + (size_t)(n + 1) * 6 + 4);
                    float p50 = __ldg(gp + (size_t)n * 6 + 5), p51 = __ldg(gp + (size_t)(n + 1) * 6 + 5);
                    float g0 = 0.25f * (li0 * c0 + 0.5f * sinf(p30 * c0 + p40) + 0.5f * cosf(p50 * c0));
                    float g1 = 0.25f * (li1 * c1 + 0.5f * sinf(p31 * c1 + p41) + 0.5f * cosf(p51 * c1));
                    vx = (c0 + 0.3f * g0 + 0.2f * vx) * (1.f / 1.5f);
                    vy = (c1 + 0.3f * g1 + 0.2f * vy) * (1.f / 1.5f);
                } else if (EPI == 4) {
                    bf162 axh = *(const bf162*)(auxh + (size_t)m * N + n);
                    bf162 axl = *(const bf162*)(auxl + (size_t)m * N + n);
                    vx = join2(axh.x, axl.x) + 0.1f * vx;
                    vy = join2(axh.y, axl.y) + 0.1f * vy;
                }

                if (MIX) {
                    bf162 rh = *(const bf162*)(resh + (size_t)m * N + n);
                    bf162 rl = *(const bf162*)(resl + (size_t)m * N + n);
                    vx = alpha * vx + beta * join2(rh.x, rl.x);
                    vy = alpha * vy + beta * join2(rh.y, rl.y);
                    part += vx * vx + vy * vy;
                    acc[mt][nt][2 * h]     = vx;
                    acc[mt][nt][2 * h + 1] = vy;
                } else {
                    bf162 lo;
                    bf162 hi = split_hi2(vx, vy, lo);
                    *(bf162*)(outh + (size_t)m * N + n) = hi;
                    *(bf162*)(outl + (size_t)m * N + n) = lo;
                }
            }
            if (MIX) {
                part += __shfl_xor_sync(0xffffffffu, part, 1);
                part += __shfl_xor_sync(0xffffffffu, part, 2);
                if (l2q == 0) red[mrow * 4 + warp_n] = part;
            }
        }
    }

    if (MIX) {
        __syncthreads();
#pragma unroll
        for (int mt = 0; mt < 2; mt++) {
#pragma unroll
            for (int h = 0; h < 2; h++) {
                const int mrow = warp_m * 32 + mt * 16 + h * 8 + l4;
                const int m = m0 + mrow;
                float ss = red[mrow * 4] + red[mrow * 4 + 1] + red[mrow * 4 + 2] + red[mrow * 4 + 3];
                float inv = 1.f / (sqrtf(ss) + 1e-8f);
#pragma unroll
                for (int nt = 0; nt < 8; nt++) {
                    const int n = n0 + warp_n * 64 + nt * 8 + l2;
                    float vx = tanhf(acc[mt][nt][2 * h] * inv);
                    float vy = tanhf(acc[mt][nt][2 * h + 1] * inv);
                    if (OUTF32) {
                        *(float2*)(outf + (size_t)m * N + n) = make_float2(vx, vy);
                    } else {
                        bf162 lo;
                        bf162 hi = split_hi2(vx, vy, lo);
                        *(bf162*)(outh + (size_t)m * N + n) = hi;
                        *(bf162*)(outl + (size_t)m * N + n) = lo;
                    }
                }
            }
        }
    }
}

// ======================= weight prep (transpose + split + optional tanh) ====
struct WMeta { const float* src; long long dst; int ldsrc; int K; int N; int op; };
struct WTable { WMeta m[32]; int count; long long total; };

__global__ void wprep_kernel(WTable tb) {
    long long t = (long long)blockIdx.x * blockDim.x + threadIdx.x;
    if (t >= tb.total) return;
    int d = 0;
    long long local = t;
    for (; d < tb.count; d++) {
        long long sz = (long long)tb.m[d].K * tb.m[d].N;
        if (local < sz) break;
        local -= sz;
    }
    const WMeta& w = tb.m[d];
    int n = (int)(local / w.K);
    int k = (int)(local % w.K);
    float v = w.src[(size_t)k * w.ldsrc + n];
    if (w.op) v = tanhf(v);
    bf16 h = __float2bfloat16(v);
    bf16 l = __float2bfloat16(v - __bfloat162float(h));
    g_wh[w.dst + local] = h;
    g_wl[w.dst + local] = l;
}

// ======================= attention fold: Wfold = Wv @ Wo, bfold = bv@Wo + bo
__global__ void afold_kernel(const float* __restrict__ awqkv,
                             const float* __restrict__ abqkv,
                             const float* __restrict__ awo,
                             const float* __restrict__ abo,
                             long long dstoff) {
    int i = blockIdx.y;          // 0..1
    int k = blockIdx.x;          // 0..255
    int n = threadIdx.x;         // 0..255
    const float* Wv = awqkv + (size_t)i * 256 * 768 + 512;
    const float* Wo = awo + (size_t)i * 65536;
    float s = 0.f;
    for (int j = 0; j < 256; j++)
        s += Wv[(size_t)k * 768 + j] * Wo[(size_t)j * 256 + n];
    long long dst = dstoff + (long long)i * 65536 + (long long)n * 256 + k;
    bf16 h = __float2bfloat16(s);
    g_wh[dst] = h;
    g_wl[dst] = __float2bfloat16(s - __bfloat162float(h));
    if (k == 0) {
        float b = abo[i * 256 + n];
        for (int j = 0; j < 256; j++)
            b += abqkv[i * 768 + 512 + j] * Wo[(size_t)j * 256 + n];
        g_bfold[i * 256 + n] = b;
    }
}

// ======================= x split + lin precompute =======================
__global__ void prep2_kernel(const float* __restrict__ x, const float* __restrict__ gp) {
    size_t i = (size_t)blockIdx.x * blockDim.x + threadIdx.x;
    if (i < (size_t)BATCH * 64) {
        float4 v = ((const float4*)x)[i];
        bf162 l0, l1;
        bf162 h0 = split_hi2(v.x, v.y, l0);
        bf162 h1 = split_hi2(v.z, v.w, l1);
        ((bf162*)g_xh)[i * 2]     = h0;
        ((bf162*)g_xh)[i * 2 + 1] = h1;
        ((bf162*)g_xl)[i * 2]     = l0;
        ((bf162*)g_xl)[i * 2 + 1] = l1;
    }
    if (i < 8 * NQ) {
        const float* p = gp + i * 6;
        g_lin[i] = sinf(p[0]) + cosf(p[1]) + tanhf(p[2]);
    }
}

// ======================= LayerNorm(768) + GELU, hi/lo in -> hi/lo out ====
__global__ __launch_bounds__(256) void lngelu_kernel(const bf16* __restrict__ ih,
                                                     const bf16* __restrict__ il,
                                                     const float* __restrict__ w,
                                                     const float* __restrict__ b,
                                                     bf16* __restrict__ oh,
                                                     bf16* __restrict__ ol) {
    __shared__ float red[8];
    __shared__ float bc;
    const int row = blockIdx.x;
    const int tid = threadIdx.x;
    const size_t base = (size_t)row * 768;

    float v[3];
#pragma unroll
    for (int e = 0; e < 3; e++)
        v[e] = join2(ih[base + tid + e * 256], il[base + tid + e * 256]);

    float s = v[0] + v[1] + v[2];
    {
        int lane = tid & 31, wd = tid >> 5;
#pragma unroll
        for (int o = 16; o > 0; o >>= 1) s += __shfl_xor_sync(0xffffffffu, s, o);
        if (lane == 0) red[wd] = s;
        __syncthreads();
        if (tid < 8) {
            float t = red[tid];
#pragma unroll
            for (int o = 4; o > 0; o >>= 1) t += __shfl_xor_sync(0xffu, t, o);
            if (tid == 0) bc = t;
        }
        __syncthreads();
    }
    float mu = bc * (1.f / 768.f);
    __syncthreads();

    float d0 = v[0] - mu, d1 = v[1] - mu, d2 = v[2] - mu;
    float ss = d0 * d0 + d1 * d1 + d2 * d2;
    {
        int lane = tid & 31, wd = tid >> 5;
#pragma unroll
        for (int o = 16; o > 0; o >>= 1) ss += __shfl_xor_sync(0xffffffffu, ss, o);
        if (lane == 0) red[wd] = ss;
        __syncthreads();
        if (tid < 8) {
            float t = red[tid];
#pragma unroll
            for (int o = 4; o > 0; o >>= 1) t += __shfl_xor_sync(0xffu, t, o);
            if (tid == 0) bc = t;
        }
        __syncthreads();
    }
    float inv = rsqrtf(bc * (1.f / 768.f) + 1e-5f);

#pragma unroll
    for (int e = 0; e < 3; e++) {
        int c = tid + e * 256;
        float o = (v[e] - mu) * inv * w[c] + b[c];
        float g = 0.5f * o * (1.f + erff(o * 0.70710678118654752f));
        bf16 hh = __float2bfloat16(g);
        oh[base + c] = hh;
        ol[base + c] = __float2bfloat16(g - __bfloat162float(hh));
    }
}

// ======================= host =======================
template <int EPI, int MIX, int OUTF32>
static void launchG(const bf16* Ah, const bf16* Al, const bf16* Wh, const bf16* Wl,
                    const float* bias, bf16* outh, bf16* outl, float* outf,
                    const bf16* auxh, const bf16* auxl,
                    const bf16* resh, const bf16* resl,
                    const float* gp, const float* lin, float alpha, int K, int N) {
    cudaFuncSetAttribute(gemm_mma<EPI, MIX, OUTF32>,
                         cudaFuncAttributeMaxDynamicSharedMemorySize, SMEM_BYTES);
    dim3 grid(N / 256, BATCH / 64);
    gemm_mma<EPI, MIX, OUTF32><<<grid, 256, SMEM_BYTES>>>(
        Ah, Al, Wh, Wl, bias, outh, outl, outf, auxh, auxl, resh, resl, gp, lin, alpha, K, N);
}

extern "C" void kernel_launch(void* const* d_in, const int* in_sizes, int n_in,
                              void* d_out, int out_size) {
    const float* x     = (const float*)d_in[0];
    const float* d0w1  = (const float*)d_in[1];
    const float* d0b1  = (const float*)d_in[2];
    const float* lnw   = (const float*)d_in[3];
    const float* lnb   = (const float*)d_in[4];
    const float* d0w2  = (const float*)d_in[5];
    const float* d0b2  = (const float*)d_in[6];
    const float* d1w1  = (const float*)d_in[7];
    const float* d1b1  = (const float*)d_in[8];
    const float* d1w2  = (const float*)d_in[9];
    const float* d1b2  = (const float*)d_in[10];
    const float* awqkv = (const float*)d_in[11];
    const float* abqkv = (const float*)d_in[12];
    const float* awo   = (const float*)d_in[13];
    const float* abo   = (const float*)d_in[14];
    const float* gp    = (const float*)d_in[15];
    const float* ent   = (const float*)d_in[16];
    const float* nlw1  = (const float*)d_in[17];
    const float* nlb1  = (const float*)d_in[18];
    const float* nlw2  = (const float*)d_in[19];
    const float* nlb2  = (const float*)d_in[20];

    float *lin, *bfold;
    bf16 *xh, *xl, *Ah, *Al, *Bh, *Bl, *h0h, *h0l, *hh, *hl, *t2h, *t2l, *t3h, *t3l, *wh, *wl;
    cudaGetSymbolAddress((void**)&lin,   g_lin);
    cudaGetSymbolAddress((void**)&bfold, g_bfold);
    cudaGetSymbolAddress((void**)&xh,    g_xh);
    cudaGetSymbolAddress((void**)&xl,    g_xl);
    cudaGetSymbolAddress((void**)&Ah,    g_Ah);
    cudaGetSymbolAddress((void**)&Al,    g_Al);
    cudaGetSymbolAddress((void**)&Bh,    g_Bh2);
    cudaGetSymbolAddress((void**)&Bl,    g_Bl2);
    cudaGetSymbolAddress((void**)&h0h,   g_h0h);
    cudaGetSymbolAddress((void**)&h0l,   g_h0l);
    cudaGetSymbolAddress((void**)&hh,    g_hh);
    cudaGetSymbolAddress((void**)&hl,    g_hl);
    cudaGetSymbolAddress((void**)&t2h,   g_t2h);
    cudaGetSymbolAddress((void**)&t2l,   g_t2l);
    cudaGetSymbolAddress((void**)&t3h,   g_t3h);
    cudaGetSymbolAddress((void**)&t3l,   g_t3l);
    cudaGetSymbolAddress((void**)&wh,    g_wh);
    cudaGetSymbolAddress((void**)&wl,    g_wl);

    // ---- weight table (dst layout: [N][K], k contiguous) ----
    WTable tb;
    long long off = 0;
    int c = 0;
    size_t o_d0w1[3], o_d0w2[3], o_d1w1[3], o_d1w2[3], o_ent[8], o_n1[4], o_n2[4];
    for (int i = 0; i < 3; i++) { o_d0w1[i] = off; tb.m[c++] = {d0w1 + (size_t)i * 256 * 768, off, 768, 256, 768, 0}; off += 256LL * 768; }
    for (int i = 0; i < 3; i++) { o_d0w2[i] = off; tb.m[c++] = {d0w2 + (size_t)i * 768 * 256, off, 256, 768, 256, 0}; off += 768LL * 256; }
    for (int i = 0; i < 3; i++) { o_d1w1[i] = off; tb.m[c++] = {d1w1 + (size_t)i * 256 * 512, off, 512, 256, 512, 0}; off += 256LL * 512; }
    for (int i = 0; i < 3; i++) { o_d1w2[i] = off; tb.m[c++] = {d1w2 + (size_t)i * 512 * 256, off, 256, 512, 256, 0}; off += 512LL * 256; }
    for (int i = 0; i < 8; i++) { o_ent[i]  = off; tb.m[c++] = {ent + (size_t)i * 256 * 256, off, 256, 256, 256, 1}; off += 256LL * 256; }
    for (int i = 0; i < 4; i++) { o_n1[i]   = off; tb.m[c++] = {nlw1 + (size_t)i * 256 * 256, off, 256, 256, 256, 0}; off += 256LL * 256; }
    for (int i = 0; i < 4; i++) { o_n2[i]   = off; tb.m[c++] = {nlw2 + (size_t)i * 256 * 256, off, 256, 256, 256, 0}; off += 256LL * 256; }
    tb.count = c;
    tb.total = off;
    long long o_fold = off;   // + i*65536

    wprep_kernel<<<(unsigned)((off + 255) / 256), 256>>>(tb);
    afold_kernel<<<dim3(256, 2), 256>>>(awqkv, abqkv, awo, abo, o_fold);
    prep2_kernel<<<(BATCH * 64 + 255) / 256, 256>>>(x, gp);

    const bf16* curh = xh;
    const bf16* curl = xl;

    for (int li = 0; li < 8; li++) {
        bf16* nxth = (li & 1) ? Bh : Ah;
        bf16* nxtl = (li & 1) ? Bl : Al;
        float alpha = (li < 4) ? 0.8f : 0.6f;
        int t = li % 3;

        if (t == 0) {
            int i = li / 3;
            launchG<0,0,0>(curh, curl, wh + o_d0w1[i], wl + o_d0w1[i], d0b1 + (size_t)i * 768,
                           h0h, h0l, nullptr, nullptr, nullptr, nullptr, nullptr,
                           nullptr, nullptr, 0.f, 256, 768);
            lngelu_kernel<<<BATCH, 256>>>(h0h, h0l, lnw + (size_t)i * 768, lnb + (size_t)i * 768, hh, hl);
            launchG<0,0,0>(hh, hl, wh + o_d0w2[i], wl + o_d0w2[i], d0b2 + (size_t)i * 256,
                           t2h, t2l, nullptr, nullptr, nullptr, nullptr, nullptr,
                           nullptr, nullptr, 0.f, 768, 256);
        } else if (t == 1) {
            int i = (li - 1) / 3;
            launchG<1,0,0>(curh, curl, wh + o_d1w1[i], wl + o_d1w1[i], d1b1 + (size_t)i * 512,
                           hh, hl, nullptr, nullptr, nullptr, nullptr, nullptr,
                           nullptr, nullptr, 0.f, 256, 512);
            launchG<0,0,0>(hh, hl, wh + o_d1w2[i], wl + o_d1w2[i], d1b2 + (size_t)i * 256,
                           t2h, t2l, nullptr, nullptr, nullptr, nullptr, nullptr,
                           nullptr, nullptr, 0.f, 512, 256);
        } else {
            int i = (li - 2) / 3;
            launchG<0,0,0>(curh, curl, wh + o_fold + (size_t)i * 65536, wl + o_fold + (size_t)i * 65536,
                           bfold + (size_t)i * 256,
                           t2h, t2l, nullptr, nullptr, nullptr, nullptr, nullptr,
                           nullptr, nullptr, 0.f, 256, 256);
        }

        if (!(li & 1)) {
            // even layer: entangle + gate + fused mix -> next cur
            launchG<3,1,0>(t2h, t2l, wh + o_ent[li], wl + o_ent[li], nullptr,
                           nxth, nxtl, nullptr, t2h, t2l, curh, curl,
                           gp + (size_t)li * 256 * 6, lin + (size_t)li * 256, alpha, 256, 256);
        } else {
            int j = li / 2;
            launchG<3,0,0>(t2h, t2l, wh + o_ent[li], wl + o_ent[li], nullptr,
                           t3h, t3l, nullptr, t2h, t2l, nullptr, nullptr,
                           gp + (size_t)li * 256 * 6, lin + (size_t)li * 256, 0.f, 256, 256);
            launchG<2,0,0>(t3h, t3l, wh + o_n1[j], wl + o_n1[j], nlb1 + (size_t)j * 256,
                           t2h, t2l, nullptr, nullptr, nullptr, nullptr, nullptr,
                           nullptr, nullptr, 0.f, 256, 256);
            if (li == 7) {
                launchG<4,1,1>(t2h, t2l, wh + o_n2[j], wl + o_n2[j], nlb2 + (size_t)j * 256,
                               nullptr, nullptr, (float*)d_out, t3h, t3l, curh, curl,
                               nullptr, nullptr, alpha, 256, 256);
            } else {
                launchG<4,1,0>(t2h, t2l, wh + o_n2[j], wl + o_n2[j], nlb2 + (size_t)j * 256,
                               nxth, nxtl, nullptr, t3h, t3l, curh, curl,
                               nullptr, nullptr, alpha, 256, 256);
            }
        }
        curh = nxth; curl = nxtl;
    }
}

// round 10
// speedup vs baseline: 1.1407x; 1.1407x over previous
#include <cuda_runtime.h>
#include <cuda_bf16.h>
#include <math.h>
#include <stdint.h>

#define BATCH 65536
#define NQ    256

typedef __nv_bfloat16  bf16;
typedef __nv_bfloat162 bf162;

// ======================= scratch (device globals) =======================
__device__ __align__(256) float g_lin  [8 * NQ];
__device__ __align__(256) float g_bfold[2 * NQ];

__device__ __align__(256) bf16 g_xh [BATCH * NQ];
__device__ __align__(256) bf16 g_xl [BATCH * NQ];
__device__ __align__(256) bf16 g_Ah [BATCH * NQ];
__device__ __align__(256) bf16 g_Al [BATCH * NQ];
__device__ __align__(256) bf16 g_Bh2[BATCH * NQ];
__device__ __align__(256) bf16 g_Bl2[BATCH * NQ];
__device__ __align__(256) bf16 g_h0h[BATCH * 768];
__device__ __align__(256) bf16 g_h0l[BATCH * 768];
__device__ __align__(256) bf16 g_hh [BATCH * 768];
__device__ __align__(256) bf16 g_hl [BATCH * 768];
__device__ __align__(256) bf16 g_t2h[BATCH * NQ];
__device__ __align__(256) bf16 g_t2l[BATCH * NQ];
__device__ __align__(256) bf16 g_t3h[BATCH * NQ];
__device__ __align__(256) bf16 g_t3l[BATCH * NQ];

#define WTOT 3276800
__device__ __align__(256) bf16 g_wh[WTOT];
__device__ __align__(256) bf16 g_wl[WTOT];

// ======================= helpers =======================
__device__ __forceinline__ uint32_t smem_u32(const void* p) {
    uint32_t a;
    asm("{ .reg .u64 t; cvta.to.shared.u64 t, %1; cvt.u32.u64 %0, t; }" : "=r"(a) : "l"(p));
    return a;
}

#define CP_ASYNC16(dst, src) \
    asm volatile("cp.async.cg.shared.global [%0], [%1], 16;" :: "r"(dst), "l"(src) : "memory")
#define CP_COMMIT() asm volatile("cp.async.commit_group;" ::: "memory")
#define CP_WAIT1()  asm volatile("cp.async.wait_group 1;" ::: "memory")

#define LDSM4(r0, r1, r2, r3, addr) \
    asm volatile("ldmatrix.sync.aligned.m8n8.x4.shared.b16 {%0,%1,%2,%3}, [%4];" \
        : "=r"(r0), "=r"(r1), "=r"(r2), "=r"(r3) : "r"(addr))

__device__ __forceinline__ void mma_bf16(float* d, const uint32_t* a, const uint32_t* b) {
    asm volatile(
        "mma.sync.aligned.m16n8k16.row.col.f32.bf16.bf16.f32 "
        "{%0,%1,%2,%3}, {%4,%5,%6,%7}, {%8,%9}, {%0,%1,%2,%3};"
        : "+f"(d[0]), "+f"(d[1]), "+f"(d[2]), "+f"(d[3])
        : "r"(a[0]), "r"(a[1]), "r"(a[2]), "r"(a[3]), "r"(b[0]), "r"(b[1]));
}

__device__ __forceinline__ bf162 split_hi2(float a, float b, bf162& lo) {
    bf16 ha = __float2bfloat16(a);
    bf16 hb = __float2bfloat16(b);
    bf16 la = __float2bfloat16(a - __bfloat162float(ha));
    bf16 lb = __float2bfloat16(b - __bfloat162float(hb));
    lo = __halves2bfloat162(la, lb);
    return __halves2bfloat162(ha, hb);
}
__device__ __forceinline__ float join2(bf16 h, bf16 l) {
    return __bfloat162float(h) + __bfloat162float(l);
}

// ======================= smem layout (tile 128 M x 256 N, k-chunk 32) ====
// pitch 80 B per row (32 bf16 data + pad) -> LDSM conflict-free
#define ST_AH 0
#define ST_AL 10240
#define ST_BH 20480
#define ST_BL 40960
#define STAGE_BYTES 61440
#define STAGES 3
#define SMEM_BYTES (STAGES * STAGE_BYTES)    // 184320

// ======================= mma.sync GEMM =======================
// C[128-row tile x 256-col tile] = epi(A @ W^T + bias), optional fused mix.
// A hi/lo bf16 [B x K]; W hi/lo bf16 [N x K] (k contiguous).
// EPI: 0 bias, 1 silu, 2 tanh, 3 gate+entangle, 4 nl-residual
// MIX: fuse alpha-mix with res + row L2-normalize + tanh (requires tile N == N)
// OUTF32: mix writes f32 (d_out) instead of hi/lo
template <int EPI, int MIX, int OUTF32>
__global__ __launch_bounds__(512, 1) void gemm_mma(
    const bf16* __restrict__ Ah, const bf16* __restrict__ Al,
    const bf16* __restrict__ Bh, const bf16* __restrict__ Bl,
    const float* __restrict__ bias,
    bf16* __restrict__ outh, bf16* __restrict__ outl, float* __restrict__ outf,
    const bf16* __restrict__ auxh, const bf16* __restrict__ auxl,
    const bf16* __restrict__ resh, const bf16* __restrict__ resl,
    const float* __restrict__ gp, const float* __restrict__ lin,
    float alpha, int K, int N)
{
    extern __shared__ char sm[];
    const uint32_t smem_base = smem_u32(sm);

    const int tid    = threadIdx.x;
    const int wid    = tid >> 5;
    const int lane   = tid & 31;
    const int warp_m = wid & 3;        // 4 warps over M: 32 rows each
    const int warp_n = wid >> 2;       // 4 warps over N: 64 cols each
    const int m0     = blockIdx.y * 128;
    const int n0     = blockIdx.x * 256;

    float acc[2][8][4];
#pragma unroll
    for (int a = 0; a < 2; a++)
#pragma unroll
        for (int b = 0; b < 8; b++)
#pragma unroll
            for (int c = 0; c < 4; c++) acc[a][b][c] = 0.f;

    const int nk = K >> 5;

    auto load_stage = [&](int stage, int kblk) {
        const int k0 = kblk << 5;
        const uint32_t sb = smem_base + stage * STAGE_BYTES;
#pragma unroll
        for (int part = 0; part < 6; part++) {
            int id = tid + part * 512;          // 0..3071
            if (id < 1024) {
                int mat = id >> 9;              // 0 Ah, 1 Al
                int rem = id & 511;
                int row = rem >> 2, ch = rem & 3;
                const bf16* s = (mat == 0 ? Ah : Al) + (size_t)(m0 + row) * K + k0 + ch * 8;
                CP_ASYNC16(sb + mat * 10240 + row * 80 + ch * 16, s);
            } else {
                int id2 = id - 1024;
                int mat = id2 >> 10;            // 0 Bh, 1 Bl
                int rem = id2 & 1023;
                int row = rem >> 2, ch = rem & 3;
                const bf16* s = (mat == 0 ? Bh : Bl) + (size_t)(n0 + row) * K + k0 + ch * 8;
                CP_ASYNC16(sb + ST_BH + mat * 20480 + row * 80 + ch * 16, s);
            }
        }
    };

    load_stage(0, 0); CP_COMMIT();
    load_stage(1, 1); CP_COMMIT();

    const uint32_t a_lane_off = (warp_m * 32 + (lane & 15)) * 80 + ((lane >> 4) << 4);
    const uint32_t b_lane_off = (warp_n * 64 + (lane & 7) + ((lane >> 4) << 3)) * 80
                              + (((lane >> 3) & 1) << 4);

    int st = 0;
    for (int i = 0; i < nk; i++) {
        CP_WAIT1();
        __syncthreads();
        {
            int st2 = st + 2; if (st2 >= 3) st2 -= 3;
            if (i + 2 < nk) load_stage(st2, i + 2);
            CP_COMMIT();
        }
        const uint32_t sb = smem_base + st * STAGE_BYTES;
#pragma unroll
        for (int kk = 0; kk < 2; kk++) {
            const uint32_t koff = kk * 32;
            uint32_t af_h[2][4], af_l[2][4];
#pragma unroll
            for (int mt = 0; mt < 2; mt++) {
                uint32_t off = a_lane_off + mt * 1280 + koff;
                LDSM4(af_h[mt][0], af_h[mt][1], af_h[mt][2], af_h[mt][3], sb + ST_AH + off);
                LDSM4(af_l[mt][0], af_l[mt][1], af_l[mt][2], af_l[mt][3], sb + ST_AL + off);
            }
#pragma unroll
            for (int p = 0; p < 4; p++) {
                uint32_t bh[2][2], bl[2][2];
                uint32_t off = b_lane_off + p * 1280 + koff;
                LDSM4(bh[0][0], bh[0][1], bh[1][0], bh[1][1], sb + ST_BH + off);
                LDSM4(bl[0][0], bl[0][1], bl[1][0], bl[1][1], sb + ST_BL + off);
#pragma unroll
                for (int mt = 0; mt < 2; mt++)
#pragma unroll
                    for (int q = 0; q < 2; q++) {
                        const int nt = p * 2 + q;
                        mma_bf16(acc[mt][nt], af_h[mt], bh[q]);
                        mma_bf16(acc[mt][nt], af_l[mt], bh[q]);
                        mma_bf16(acc[mt][nt], af_h[mt], bl[q]);
                    }
            }
        }
        st++; if (st >= 3) st = 0;
    }

    // ---------- epilogue ----------
    __syncthreads();                         // allow smem reuse for reduction
    float* red = (float*)sm;                 // [128 rows][4 warp_n]

    const int l4  = lane >> 2;
    const int l2q = lane & 3;
    const int l2  = l2q * 2;
    const float beta = 1.f - alpha;

#pragma unroll
    for (int mt = 0; mt < 2; mt++) {
#pragma unroll
        for (int h = 0; h < 2; h++) {
            const int mrow = warp_m * 32 + mt * 16 + h * 8 + l4;
            const int m = m0 + mrow;
            float part = 0.f;
#pragma unroll
            for (int nt = 0; nt < 8; nt++) {
                const int n = n0 + warp_n * 64 + nt * 8 + l2;
                float vx = acc[mt][nt][2 * h];
                float vy = acc[mt][nt][2 * h + 1];

                if (EPI != 3) {
                    float2 b2 = *(const float2*)(bias + n);
                    vx += b2.x; vy += b2.y;
                }
                if (EPI == 1) {
                    vx = vx / (1.f + expf(-vx));
                    vy = vy / (1.f + expf(-vy));
                } else if (EPI == 2) {
                    vx = tanhf(vx);
                    vy = tanhf(vy);
                } else if (EPI == 3) {
                    bf162 axh = *(const bf162*)(auxh + (size_t)m * N + n);
                    bf162 axl = *(const bf162*)(auxl + (size_t)m * N + n);
                    float c0 = join2(axh.x, axl.x);
                    float c1 = join2(axh.y, axl.y);
                    float li0 = __ldg(lin + n),     li1 = __ldg(lin + n + 1);
                    float p30 = __ldg(gp + (size_t)n * 6 + 3), p31 = __ldg(gp + (size_t)(n + 1) * 6 + 3);
                    float p40 = __ldg(gp + (size_t)n * 6 + 4), p41 = __ldg(gp + (size_t)(n + 1) * 6 + 4);
                    float p50 = __ldg(gp + (size_t)n * 6 + 5), p51 = __ldg(gp + (size_t)(n + 1) * 6 + 5);
                    float g0 = 0.25f * (li0 * c0 + 0.5f * sinf(p30 * c0 + p40) + 0.5f * cosf(p50 * c0));
                    float g1 = 0.25f * (li1 * c1 + 0.5f * sinf(p31 * c1 + p41) + 0.5f * cosf(p51 * c1));
                    vx = (c0 + 0.3f * g0 + 0.2f * vx) * (1.f / 1.5f);
                    vy = (c1 + 0.3f * g1 + 0.2f * vy) * (1.f / 1.5f);
                } else if (EPI == 4) {
                    bf162 axh = *(const bf162*)(auxh + (size_t)m * N + n);
                    bf162 axl = *(const bf162*)(auxl + (size_t)m * N + n);
                    vx = join2(axh.x, axl.x) + 0.1f * vx;
                    vy = join2(axh.y, axl.y) + 0.1f * vy;
                }

                if (MIX) {
                    bf162 rh = *(const bf162*)(resh + (size_t)m * N + n);
                    bf162 rl = *(const bf162*)(resl + (size_t)m * N + n);
                    vx = alpha * vx + beta * join2(rh.x, rl.x);
                    vy = alpha * vy + beta * join2(rh.y, rl.y);
                    part += vx * vx + vy * vy;
                    acc[mt][nt][2 * h]     = vx;
                    acc[mt][nt][2 * h + 1] = vy;
                } else {
                    bf162 lo;
                    bf162 hi = split_hi2(vx, vy, lo);
                    *(bf162*)(outh + (size_t)m * N + n) = hi;
                    *(bf162*)(outl + (size_t)m * N + n) = lo;
                }
            }
            if (MIX) {
                part += __shfl_xor_sync(0xffffffffu, part, 1);
                part += __shfl_xor_sync(0xffffffffu, part, 2);
                if (l2q == 0) red[mrow * 4 + warp_n] = part;
            }
        }
    }

    if (MIX) {
        __syncthreads();
#pragma unroll
        for (int mt = 0; mt < 2; mt++) {
#pragma unroll
            for (int h = 0; h < 2; h++) {
                const int mrow = warp_m * 32 + mt * 16 + h * 8 + l4;
                const int m = m0 + mrow;
                float ss = red[mrow * 4] + red[mrow * 4 + 1] + red[mrow * 4 + 2] + red[mrow * 4 + 3];
                float inv = 1.f / (sqrtf(ss) + 1e-8f);
#pragma unroll
                for (int nt = 0; nt < 8; nt++) {
                    const int n = n0 + warp_n * 64 + nt * 8 + l2;
                    float vx = tanhf(acc[mt][nt][2 * h] * inv);
                    float vy = tanhf(acc[mt][nt][2 * h + 1] * inv);
                    if (OUTF32) {
                        *(float2*)(outf + (size_t)m * N + n) = make_float2(vx, vy);
                    } else {
                        bf162 lo;
                        bf162 hi = split_hi2(vx, vy, lo);
                        *(bf162*)(outh + (size_t)m * N + n) = hi;
                        *(bf162*)(outl + (size_t)m * N + n) = lo;
                    }
                }
            }
        }
    }
}

// ======================= weight prep (transpose + split + optional tanh) ====
struct WMeta { const float* src; long long dst; int ldsrc; int K; int N; int op; };
struct WTable { WMeta m[32]; int count; long long total; };

__global__ void wprep_kernel(WTable tb) {
    long long t = (long long)blockIdx.x * blockDim.x + threadIdx.x;
    if (t >= tb.total) return;
    int d = 0;
    long long local = t;
    for (; d < tb.count; d++) {
        long long sz = (long long)tb.m[d].K * tb.m[d].N;
        if (local < sz) break;
        local -= sz;
    }
    const WMeta& w = tb.m[d];
    int n = (int)(local / w.K);
    int k = (int)(local % w.K);
    float v = w.src[(size_t)k * w.ldsrc + n];
    if (w.op) v = tanhf(v);
    bf16 h = __float2bfloat16(v);
    bf16 l = __float2bfloat16(v - __bfloat162float(h));
    g_wh[w.dst + local] = h;
    g_wl[w.dst + local] = l;
}

// ======================= attention fold: Wfold = Wv @ Wo, bfold = bv@Wo + bo
__global__ void afold_kernel(const float* __restrict__ awqkv,
                             const float* __restrict__ abqkv,
                             const float* __restrict__ awo,
                             const float* __restrict__ abo,
                             long long dstoff) {
    int i = blockIdx.y;          // 0..1
    int k = blockIdx.x;          // 0..255
    int n = threadIdx.x;         // 0..255
    const float* Wv = awqkv + (size_t)i * 256 * 768 + 512;
    const float* Wo = awo + (size_t)i * 65536;
    float s = 0.f;
    for (int j = 0; j < 256; j++)
        s += Wv[(size_t)k * 768 + j] * Wo[(size_t)j * 256 + n];
    long long dst = dstoff + (long long)i * 65536 + (long long)n * 256 + k;
    bf16 h = __float2bfloat16(s);
    g_wh[dst] = h;
    g_wl[dst] = __float2bfloat16(s - __bfloat162float(h));
    if (k == 0) {
        float b = abo[i * 256 + n];
        for (int j = 0; j < 256; j++)
            b += abqkv[i * 768 + 512 + j] * Wo[(size_t)j * 256 + n];
        g_bfold[i * 256 + n] = b;
    }
}

// ======================= x split + lin precompute =======================
__global__ void prep2_kernel(const float* __restrict__ x, const float* __restrict__ gp) {
    size_t i = (size_t)blockIdx.x * blockDim.x + threadIdx.x;
    if (i < (size_t)BATCH * 64) {
        float4 v = ((const float4*)x)[i];
        bf162 l0, l1;
        bf162 h0 = split_hi2(v.x, v.y, l0);
        bf162 h1 = split_hi2(v.z, v.w, l1);
        ((bf162*)g_xh)[i * 2]     = h0;
        ((bf162*)g_xh)[i * 2 + 1] = h1;
        ((bf162*)g_xl)[i * 2]     = l0;
        ((bf162*)g_xl)[i * 2 + 1] = l1;
    }
    if (i < 8 * NQ) {
        const float* p = gp + i * 6;
        g_lin[i] = sinf(p[0]) + cosf(p[1]) + tanhf(p[2]);
    }
}

// ======================= LayerNorm(768) + GELU, hi/lo in -> hi/lo out ====
__global__ __launch_bounds__(256) void lngelu_kernel(const bf16* __restrict__ ih,
                                                     const bf16* __restrict__ il,
                                                     const float* __restrict__ w,
                                                     const float* __restrict__ b,
                                                     bf16* __restrict__ oh,
                                                     bf16* __restrict__ ol) {
    __shared__ float red[8];
    __shared__ float bc;
    const int row = blockIdx.x;
    const int tid = threadIdx.x;
    const size_t base = (size_t)row * 768;

    float v[3];
#pragma unroll
    for (int e = 0; e < 3; e++)
        v[e] = join2(ih[base + tid + e * 256], il[base + tid + e * 256]);

    float s = v[0] + v[1] + v[2];
    {
        int lane = tid & 31, wd = tid >> 5;
#pragma unroll
        for (int o = 16; o > 0; o >>= 1) s += __shfl_xor_sync(0xffffffffu, s, o);
        if (lane == 0) red[wd] = s;
        __syncthreads();
        if (tid < 8) {
            float t = red[tid];
#pragma unroll
            for (int o = 4; o > 0; o >>= 1) t += __shfl_xor_sync(0xffu, t, o);
            if (tid == 0) bc = t;
        }
        __syncthreads();
    }
    float mu = bc * (1.f / 768.f);
    __syncthreads();

    float d0 = v[0] - mu, d1 = v[1] - mu, d2 = v[2] - mu;
    float ss = d0 * d0 + d1 * d1 + d2 * d2;
    {
        int lane = tid & 31, wd = tid >> 5;
#pragma unroll
        for (int o = 16; o > 0; o >>= 1) ss += __shfl_xor_sync(0xffffffffu, ss, o);
        if (lane == 0) red[wd] = ss;
        __syncthreads();
        if (tid < 8) {
            float t = red[tid];
#pragma unroll
            for (int o = 4; o > 0; o >>= 1) t += __shfl_xor_sync(0xffu, t, o);
            if (tid == 0) bc = t;
        }
        __syncthreads();
    }
    float inv = rsqrtf(bc * (1.f / 768.f) + 1e-5f);

#pragma unroll
    for (int e = 0; e < 3; e++) {
        int c = tid + e * 256;
        float o = (v[e] - mu) * inv * w[c] + b[c];
        float g = 0.5f * o * (1.f + erff(o * 0.70710678118654752f));
        bf16 hh = __float2bfloat16(g);
        oh[base + c] = hh;
        ol[base + c] = __float2bfloat16(g - __bfloat162float(hh));
    }
}

// ======================= host =======================
template <int EPI, int MIX, int OUTF32>
static void launchG(const bf16* Ah, const bf16* Al, const bf16* Wh, const bf16* Wl,
                    const float* bias, bf16* outh, bf16* outl, float* outf,
                    const bf16* auxh, const bf16* auxl,
                    const bf16* resh, const bf16* resl,
                    const float* gp, const float* lin, float alpha, int K, int N) {
    cudaFuncSetAttribute(gemm_mma<EPI, MIX, OUTF32>,
                         cudaFuncAttributeMaxDynamicSharedMemorySize, SMEM_BYTES);
    dim3 grid(N / 256, BATCH / 128);
    gemm_mma<EPI, MIX, OUTF32><<<grid, 512, SMEM_BYTES>>>(
        Ah, Al, Wh, Wl, bias, outh, outl, outf, auxh, auxl, resh, resl, gp, lin, alpha, K, N);
}

extern "C" void kernel_launch(void* const* d_in, const int* in_sizes, int n_in,
                              void* d_out, int out_size) {
    const float* x     = (const float*)d_in[0];
    const float* d0w1  = (const float*)d_in[1];
    const float* d0b1  = (const float*)d_in[2];
    const float* lnw   = (const float*)d_in[3];
    const float* lnb   = (const float*)d_in[4];
    const float* d0w2  = (const float*)d_in[5];
    const float* d0b2  = (const float*)d_in[6];
    const float* d1w1  = (const float*)d_in[7];
    const float* d1b1  = (const float*)d_in[8];
    const float* d1w2  = (const float*)d_in[9];
    const float* d1b2  = (const float*)d_in[10];
    const float* awqkv = (const float*)d_in[11];
    const float* abqkv = (const float*)d_in[12];
    const float* awo   = (const float*)d_in[13];
    const float* abo   = (const float*)d_in[14];
    const float* gp    = (const float*)d_in[15];
    const float* ent   = (const float*)d_in[16];
    const float* nlw1  = (const float*)d_in[17];
    const float* nlb1  = (const float*)d_in[18];
    const float* nlw2  = (const float*)d_in[19];
    const float* nlb2  = (const float*)d_in[20];

    float *lin, *bfold;
    bf16 *xh, *xl, *Ah, *Al, *Bh, *Bl, *h0h, *h0l, *hh, *hl, *t2h, *t2l, *t3h, *t3l, *wh, *wl;
    cudaGetSymbolAddress((void**)&lin,   g_lin);
    cudaGetSymbolAddress((void**)&bfold, g_bfold);
    cudaGetSymbolAddress((void**)&xh,    g_xh);
    cudaGetSymbolAddress((void**)&xl,    g_xl);
    cudaGetSymbolAddress((void**)&Ah,    g_Ah);
    cudaGetSymbolAddress((void**)&Al,    g_Al);
    cudaGetSymbolAddress((void**)&Bh,    g_Bh2);
    cudaGetSymbolAddress((void**)&Bl,    g_Bl2);
    cudaGetSymbolAddress((void**)&h0h,   g_h0h);
    cudaGetSymbolAddress((void**)&h0l,   g_h0l);
    cudaGetSymbolAddress((void**)&hh,    g_hh);
    cudaGetSymbolAddress((void**)&hl,    g_hl);
    cudaGetSymbolAddress((void**)&t2h,   g_t2h);
    cudaGetSymbolAddress((void**)&t2l,   g_t2l);
    cudaGetSymbolAddress((void**)&t3h,   g_t3h);
    cudaGetSymbolAddress((void**)&t3l,   g_t3l);
    cudaGetSymbolAddress((void**)&wh,    g_wh);
    cudaGetSymbolAddress((void**)&wl,    g_wl);

    // ---- weight table (dst layout: [N][K], k contiguous) ----
    WTable tb;
    long long off = 0;
    int c = 0;
    size_t o_d0w1[3], o_d0w2[3], o_d1w1[3], o_d1w2[3], o_ent[8], o_n1[4], o_n2[4];
    for (int i = 0; i < 3; i++) { o_d0w1[i] = off; tb.m[c++] = {d0w1 + (size_t)i * 256 * 768, off, 768, 256, 768, 0}; off += 256LL * 768; }
    for (int i = 0; i < 3; i++) { o_d0w2[i] = off; tb.m[c++] = {d0w2 + (size_t)i * 768 * 256, off, 256, 768, 256, 0}; off += 768LL * 256; }
    for (int i = 0; i < 3; i++) { o_d1w1[i] = off; tb.m[c++] = {d1w1 + (size_t)i * 256 * 512, off, 512, 256, 512, 0}; off += 256LL * 512; }
    for (int i = 0; i < 3; i++) { o_d1w2[i] = off; tb.m[c++] = {d1w2 + (size_t)i * 512 * 256, off, 256, 512, 256, 0}; off += 512LL * 256; }
    for (int i = 0; i < 8; i++) { o_ent[i]  = off; tb.m[c++] = {ent + (size_t)i * 256 * 256, off, 256, 256, 256, 1}; off += 256LL * 256; }
    for (int i = 0; i < 4; i++) { o_n1[i]   = off; tb.m[c++] = {nlw1 + (size_t)i * 256 * 256, off, 256, 256, 256, 0}; off += 256LL * 256; }
    for (int i = 0; i < 4; i++) { o_n2[i]   = off; tb.m[c++] = {nlw2 + (size_t)i * 256 * 256, off, 256, 256, 256, 0}; off += 256LL * 256; }
    tb.count = c;
    tb.total = off;
    long long o_fold = off;   // + i*65536

    wprep_kernel<<<(unsigned)((off + 255) / 256), 256>>>(tb);
    afold_kernel<<<dim3(256, 2), 256>>>(awqkv, abqkv, awo, abo, o_fold);
    prep2_kernel<<<(BATCH * 64 + 255) / 256, 256>>>(x, gp);

    const bf16* curh = xh;
    const bf16* curl = xl;

    for (int li = 0; li < 8; li++) {
        bf16* nxth = (li & 1) ? Bh : Ah;
        bf16* nxtl = (li & 1) ? Bl : Al;
        float alpha = (li < 4) ? 0.8f : 0.6f;
        int t = li % 3;

        if (t == 0) {
            int i = li / 3;
            launchG<0,0,0>(curh, curl, wh + o_d0w1[i], wl + o_d0w1[i], d0b1 + (size_t)i * 768,
                           h0h, h0l, nullptr, nullptr, nullptr, nullptr, nullptr,
                           nullptr, nullptr, 0.f, 256, 768);
            lngelu_kernel<<<BATCH, 256>>>(h0h, h0l, lnw + (size_t)i * 768, lnb + (size_t)i * 768, hh, hl);
            launchG<0,0,0>(hh, hl, wh + o_d0w2[i], wl + o_d0w2[i], d0b2 + (size_t)i * 256,
                           t2h, t2l, nullptr, nullptr, nullptr, nullptr, nullptr,
                           nullptr, nullptr, 0.f, 768, 256);
        } else if (t == 1) {
            int i = (li - 1) / 3;
            launchG<1,0,0>(curh, curl, wh + o_d1w1[i], wl + o_d1w1[i], d1b1 + (size_t)i * 512,
                           hh, hl, nullptr, nullptr, nullptr, nullptr, nullptr,
                           nullptr, nullptr, 0.f, 256, 512);
            launchG<0,0,0>(hh, hl, wh + o_d1w2[i], wl + o_d1w2[i], d1b2 + (size_t)i * 256,
                           t2h, t2l, nullptr, nullptr, nullptr, nullptr, nullptr,
                           nullptr, nullptr, 0.f, 512, 256);
        } else {
            int i = (li - 2) / 3;
            launchG<0,0,0>(curh, curl, wh + o_fold + (size_t)i * 65536, wl + o_fold + (size_t)i * 65536,
                           bfold + (size_t)i * 256,
                           t2h, t2l, nullptr, nullptr, nullptr, nullptr, nullptr,
                           nullptr, nullptr, 0.f, 256, 256);
        }

        if (!(li & 1)) {
            // even layer: entangle + gate + fused mix -> next cur
            launchG<3,1,0>(t2h, t2l, wh + o_ent[li], wl + o_ent[li], nullptr,
                           nxth, nxtl, nullptr, t2h, t2l, curh, curl,
                           gp + (size_t)li * 256 * 6, lin + (size_t)li * 256, alpha, 256, 256);
        } else {
            int j = li / 2;
            launchG<3,0,0>(t2h, t2l, wh + o_ent[li], wl + o_ent[li], nullptr,
                           t3h, t3l, nullptr, t2h, t2l, nullptr, nullptr,
                           gp + (size_t)li * 256 * 6, lin + (size_t)li * 256, 0.f, 256, 256);
            launchG<2,0,0>(t3h, t3l, wh + o_n1[j], wl + o_n1[j], nlb1 + (size_t)j * 256,
                           t2h, t2l, nullptr, nullptr, nullptr, nullptr, nullptr,
                           nullptr, nullptr, 0.f, 256, 256);
            if (li == 7) {
                launchG<4,1,1>(t2h, t2l, wh + o_n2[j], wl + o_n2[j], nlb2 + (size_t)j * 256,
                               nullptr, nullptr, (float*)d_out, t3h, t3l, curh, curl,
                               nullptr, nullptr, alpha, 256, 256);
            } else {
                launchG<4,1,0>(t2h, t2l, wh + o_n2[j], wl + o_n2[j], nlb2 + (size_t)j * 256,
                               nxth, nxtl, nullptr, t3h, t3l, curh, curl,
                               nullptr, nullptr, alpha, 256, 256);
            }
        }
        curh = nxth; curl = nxtl;
    }
}

// round 11
// speedup vs baseline: 1.2479x; 1.0939x over previous
#include <cuda_runtime.h>
#include <cuda_bf16.h>
#include <math.h>
#include <stdint.h>

#define BATCH 65536
#define NQ    256

typedef __nv_bfloat16  bf16;
typedef __nv_bfloat162 bf162;

// ======================= scratch (device globals) =======================
__device__ __align__(256) float g_lin  [8 * NQ];
__device__ __align__(256) float g_bfold[2 * NQ];

__device__ __align__(256) bf16 g_xh [BATCH * NQ];
__device__ __align__(256) bf16 g_xl [BATCH * NQ];
__device__ __align__(256) bf16 g_Ah [BATCH * NQ];
__device__ __align__(256) bf16 g_Al [BATCH * NQ];
__device__ __align__(256) bf16 g_Bh2[BATCH * NQ];
__device__ __align__(256) bf16 g_Bl2[BATCH * NQ];
__device__ __align__(256) bf16 g_h0h[BATCH * 768];
__device__ __align__(256) bf16 g_h0l[BATCH * 768];
__device__ __align__(256) bf16 g_hh [BATCH * 768];
__device__ __align__(256) bf16 g_hl [BATCH * 768];
__device__ __align__(256) bf16 g_t2h[BATCH * NQ];
__device__ __align__(256) bf16 g_t2l[BATCH * NQ];
__device__ __align__(256) bf16 g_t3h[BATCH * NQ];
__device__ __align__(256) bf16 g_t3l[BATCH * NQ];

#define WTOT 3276800
__device__ __align__(256) bf16 g_wh[WTOT];
__device__ __align__(256) bf16 g_wl[WTOT];

// ======================= helpers =======================
__device__ __forceinline__ uint32_t smem_u32(const void* p) {
    uint32_t a;
    asm("{ .reg .u64 t; cvta.to.shared.u64 t, %1; cvt.u32.u64 %0, t; }" : "=r"(a) : "l"(p));
    return a;
}
__host__ __device__ __forceinline__ uint32_t sw128(uint32_t o) {
    return o ^ ((o >> 3) & 0x70);
}
// tiled activation layout: [m/128][k/64][128 rows][64 k] bf16, SW128 within 128B rows.
// returns ELEMENT index. K = feature width (multiple of 64).
__device__ __forceinline__ size_t act_idx(int m, int k, int K) {
    uint32_t o = ((uint32_t)(m & 127) << 7) + ((uint32_t)(k & 63) << 1);
    o = sw128(o);
    return ((size_t)(m >> 7) * (K >> 6) + (k >> 6)) * 8192 + (o >> 1);
}

#define CP_BULK(dst, src, bytes, mbar) \
    asm volatile("cp.async.bulk.shared::cluster.global.mbarrier::complete_tx::bytes [%0], [%1], %2, [%3];" \
        :: "r"(dst), "l"(src), "r"(bytes), "r"(mbar) : "memory")

#define MBARRIER_INIT(mbar, cnt) \
    asm volatile("mbarrier.init.shared.b64 [%0], %1;" \
        :: "r"((uint32_t)(mbar)), "r"((uint32_t)(cnt)) : "memory")
#define MBARRIER_EXPECT_TX(mbar, bytes) \
    asm volatile("mbarrier.arrive.expect_tx.shared.b64 _, [%0], %1;" \
        :: "r"((uint32_t)(mbar)), "r"((uint32_t)(bytes)) : "memory")
#define MBARRIER_WAIT_PARITY(mbar, parity) do { \
    uint32_t _mb = (uint32_t)(mbar); \
    uint32_t _pa = (uint32_t)(parity); \
    uint32_t _done; \
    asm volatile("{\n\t.reg .pred p;\n\tmbarrier.try_wait.parity.acquire.cta.shared::cta.b64 p, [%1], %2;\n\tselp.b32 %0, 1, 0, p;\n\t}" \
        : "=r"(_done) : "r"(_mb), "r"(_pa) : "memory"); \
    if (!_done) { \
        asm volatile("{\n\t.reg .pred P1;\n\tWAIT_LOOP_%=:\n\tmbarrier.try_wait.parity.acquire.cta.shared::cta.b64 P1, [%0], %1, 0x989680;\n\t@P1 bra.uni WAIT_DONE_%=;\n\tbra.uni WAIT_LOOP_%=;\n\tWAIT_DONE_%=:\n\t}" \
            :: "r"(_mb), "r"(_pa) : "memory"); \
    } \
} while (0)

#define LDSM4(r0, r1, r2, r3, addr) \
    asm volatile("ldmatrix.sync.aligned.m8n8.x4.shared.b16 {%0,%1,%2,%3}, [%4];" \
        : "=r"(r0), "=r"(r1), "=r"(r2), "=r"(r3) : "r"(addr))

__device__ __forceinline__ void mma_bf16(float* d, const uint32_t* a, const uint32_t* b) {
    asm volatile(
        "mma.sync.aligned.m16n8k16.row.col.f32.bf16.bf16.f32 "
        "{%0,%1,%2,%3}, {%4,%5,%6,%7}, {%8,%9}, {%0,%1,%2,%3};"
        : "+f"(d[0]), "+f"(d[1]), "+f"(d[2]), "+f"(d[3])
        : "r"(a[0]), "r"(a[1]), "r"(a[2]), "r"(a[3]), "r"(b[0]), "r"(b[1]));
}

__device__ __forceinline__ bf162 split_hi2(float a, float b, bf162& lo) {
    bf16 ha = __float2bfloat16(a);
    bf16 hb = __float2bfloat16(b);
    bf16 la = __float2bfloat16(a - __bfloat162float(ha));
    bf16 lb = __float2bfloat16(b - __bfloat162float(hb));
    lo = __halves2bfloat162(la, lb);
    return __halves2bfloat162(ha, hb);
}
__device__ __forceinline__ float join2(bf16 h, bf16 l) {
    return __bfloat162float(h) + __bfloat162float(l);
}

// ======================= smem layout (tile 128 M x 256 N, k-chunk 64) ====
// Stage: Ah 16K | Al 16K | Bh 32K | Bl 32K  = 96 KB. 2 stages + barriers.
#define ST_AL 16384
#define ST_BH 32768
#define ST_BL 65536
#define STAGE_BYTES 98304
#define MB_OFF (2 * STAGE_BYTES)
#define SMEM_BYTES (2 * STAGE_BYTES + 16)

// ======================= bulk-TMA mma.sync GEMM =======================
// A planes tiled [B/128][K/64][128][64] (swizzled); W planes tiled [N/256][K/64][256][64].
// EPI: 0 bias, 1 silu, 2 tanh, 3 gate+entangle, 4 nl-residual
// MIX: fused alpha-mix + row L2-normalize + tanh; OUTF32: mix writes f32 linear (d_out)
template <int EPI, int MIX, int OUTF32>
__global__ __launch_bounds__(512, 1) void gemm_mma(
    const bf16* __restrict__ Ah, const bf16* __restrict__ Al,
    const bf16* __restrict__ Bh, const bf16* __restrict__ Bl,
    const float* __restrict__ bias,
    bf16* __restrict__ outh, bf16* __restrict__ outl, float* __restrict__ outf,
    const bf16* __restrict__ auxh, const bf16* __restrict__ auxl,
    const bf16* __restrict__ resh, const bf16* __restrict__ resl,
    const float* __restrict__ gp, const float* __restrict__ lin,
    float alpha, int K, int N)
{
    extern __shared__ char sm[];
    const uint32_t smem_base = smem_u32(sm);

    const int tid    = threadIdx.x;
    const int wid    = tid >> 5;
    const int lane   = tid & 31;
    const int warp_m = wid & 3;        // 4 warps over M: 32 rows each
    const int warp_n = wid >> 2;       // 4 warps over N: 64 cols each
    const int blkm   = blockIdx.y;
    const int blkn   = blockIdx.x;
    const int m0     = blkm * 128;
    const int n0     = blkn * 256;
    const int nc     = K >> 6;

    float acc[2][8][4];
#pragma unroll
    for (int a = 0; a < 2; a++)
#pragma unroll
        for (int b = 0; b < 8; b++)
#pragma unroll
            for (int c = 0; c < 4; c++) acc[a][b][c] = 0.f;

    auto issue = [&](int s, int c) {
        uint32_t sb = smem_base + s * STAGE_BYTES;
        uint32_t mb = smem_base + MB_OFF + s * 8;
        MBARRIER_EXPECT_TX(mb, 98304);
        CP_BULK(sb,           Ah + ((size_t)blkm * nc + c) * 8192,  16384, mb);
        CP_BULK(sb + ST_AL,   Al + ((size_t)blkm * nc + c) * 8192,  16384, mb);
        CP_BULK(sb + ST_BH,   Bh + ((size_t)blkn * nc + c) * 16384, 32768, mb);
        CP_BULK(sb + ST_BL,   Bl + ((size_t)blkn * nc + c) * 16384, 32768, mb);
    };

    if (tid == 0) {
        MBARRIER_INIT(smem_base + MB_OFF, 1);
        MBARRIER_INIT(smem_base + MB_OFF + 8, 1);
    }
    __syncthreads();
    if (tid == 0) { issue(0, 0); issue(1, 1); }

    // per-lane base offsets (pre-swizzle byte offsets within a plane)
    const uint32_t oA0 = (((uint32_t)(warp_m * 32 + (lane & 15))) << 7) + ((lane >> 4) << 4);
    const uint32_t oB0 = (((uint32_t)(warp_n * 64 + (lane & 7) + ((lane >> 4) << 3))) << 7)
                       + (((lane >> 3) & 1) << 4);

    int ph0 = 0, ph1 = 0;
    for (int i = 0; i < nc; i++) {
        const int s = i & 1;
        MBARRIER_WAIT_PARITY(smem_base + MB_OFF + s * 8, s ? ph1 : ph0);
        if (s) ph1 ^= 1; else ph0 ^= 1;

        const uint32_t sb = smem_base + s * STAGE_BYTES;
#pragma unroll
        for (int kk = 0; kk < 4; kk++) {
            const uint32_t ko = kk << 5;
            uint32_t af_h[2][4], af_l[2][4];
#pragma unroll
            for (int mt = 0; mt < 2; mt++) {
                uint32_t o = oA0 + (mt << 11) + ko;
                o = sw128(o);
                LDSM4(af_h[mt][0], af_h[mt][1], af_h[mt][2], af_h[mt][3], sb + o);
                LDSM4(af_l[mt][0], af_l[mt][1], af_l[mt][2], af_l[mt][3], sb + ST_AL + o);
            }
#pragma unroll
            for (int p = 0; p < 4; p++) {
                uint32_t o = oB0 + (p << 11) + ko;
                o = sw128(o);
                uint32_t bh[2][2], bl[2][2];
                LDSM4(bh[0][0], bh[0][1], bh[1][0], bh[1][1], sb + ST_BH + o);
                LDSM4(bl[0][0], bl[0][1], bl[1][0], bl[1][1], sb + ST_BL + o);
#pragma unroll
                for (int mt = 0; mt < 2; mt++)
#pragma unroll
                    for (int q = 0; q < 2; q++) {
                        const int nt = p * 2 + q;
                        mma_bf16(acc[mt][nt], af_h[mt], bh[q]);
                        mma_bf16(acc[mt][nt], af_l[mt], bh[q]);
                        mma_bf16(acc[mt][nt], af_h[mt], bl[q]);
                    }
            }
        }
        __syncthreads();
        if (i + 2 < nc && tid == 0) issue(s, i + 2);
    }

    // ---------- epilogue ----------
    float* red = (float*)sm;                 // [128 rows][4 warp_n] (stage smem reused)

    const int l4  = lane >> 2;
    const int l2q = lane & 3;
    const int l2  = l2q * 2;
    const float beta = 1.f - alpha;

#pragma unroll
    for (int mt = 0; mt < 2; mt++) {
#pragma unroll
        for (int h = 0; h < 2; h++) {
            const int mrow = warp_m * 32 + mt * 16 + h * 8 + l4;
            const int m = m0 + mrow;
            float part = 0.f;
#pragma unroll
            for (int nt = 0; nt < 8; nt++) {
                const int n = n0 + warp_n * 64 + nt * 8 + l2;
                float vx = acc[mt][nt][2 * h];
                float vy = acc[mt][nt][2 * h + 1];

                if (EPI != 3) {
                    float2 b2 = *(const float2*)(bias + n);
                    vx += b2.x; vy += b2.y;
                }
                if (EPI == 1) {
                    vx = vx / (1.f + expf(-vx));
                    vy = vy / (1.f + expf(-vy));
                } else if (EPI == 2) {
                    vx = tanhf(vx);
                    vy = tanhf(vy);
                } else if (EPI == 3) {
                    size_t ai = act_idx(m, n, N);
                    bf162 axh = *(const bf162*)(auxh + ai);
                    bf162 axl = *(const bf162*)(auxl + ai);
                    float c0 = join2(axh.x, axl.x);
                    float c1 = join2(axh.y, axl.y);
                    float li0 = __ldg(lin + n),     li1 = __ldg(lin + n + 1);
                    float p30 = __ldg(gp + (size_t)n * 6 + 3), p31 = __ldg(gp + (size_t)(n + 1) * 6 + 3);
                    float p40 = __ldg(gp + (size_t)n * 6 + 4), p41 = __ldg(gp + (size_t)(n + 1) * 6 + 4);
                    float p50 = __ldg(gp + (size_t)n * 6 + 5), p51 = __ldg(gp + (size_t)(n + 1) * 6 + 5);
                    float g0 = 0.25f * (li0 * c0 + 0.5f * sinf(p30 * c0 + p40) + 0.5f * cosf(p50 * c0));
                    float g1 = 0.25f * (li1 * c1 + 0.5f * sinf(p31 * c1 + p41) + 0.5f * cosf(p51 * c1));
                    vx = (c0 + 0.3f * g0 + 0.2f * vx) * (1.f / 1.5f);
                    vy = (c1 + 0.3f * g1 + 0.2f * vy) * (1.f / 1.5f);
                } else if (EPI == 4) {
                    size_t ai = act_idx(m, n, N);
                    bf162 axh = *(const bf162*)(auxh + ai);
                    bf162 axl = *(const bf162*)(auxl + ai);
                    vx = join2(axh.x, axl.x) + 0.1f * vx;
                    vy = join2(axh.y, axl.y) + 0.1f * vy;
                }

                if (MIX) {
                    size_t ri = act_idx(m, n, N);
                    bf162 rh = *(const bf162*)(resh + ri);
                    bf162 rl = *(const bf162*)(resl + ri);
                    vx = alpha * vx + beta * join2(rh.x, rl.x);
                    vy = alpha * vy + beta * join2(rh.y, rl.y);
                    part += vx * vx + vy * vy;
                    acc[mt][nt][2 * h]     = vx;
                    acc[mt][nt][2 * h + 1] = vy;
                } else {
                    bf162 lo;
                    bf162 hi = split_hi2(vx, vy, lo);
                    size_t oi = act_idx(m, n, N);
                    *(bf162*)(outh + oi) = hi;
                    *(bf162*)(outl + oi) = lo;
                }
            }
            if (MIX) {
                part += __shfl_xor_sync(0xffffffffu, part, 1);
                part += __shfl_xor_sync(0xffffffffu, part, 2);
                if (l2q == 0) red[mrow * 4 + warp_n] = part;
            }
        }
    }

    if (MIX) {
        __syncthreads();
#pragma unroll
        for (int mt = 0; mt < 2; mt++) {
#pragma unroll
            for (int h = 0; h < 2; h++) {
                const int mrow = warp_m * 32 + mt * 16 + h * 8 + l4;
                const int m = m0 + mrow;
                float ss = red[mrow * 4] + red[mrow * 4 + 1] + red[mrow * 4 + 2] + red[mrow * 4 + 3];
                float inv = 1.f / (sqrtf(ss) + 1e-8f);
#pragma unroll
                for (int nt = 0; nt < 8; nt++) {
                    const int n = n0 + warp_n * 64 + nt * 8 + l2;
                    float vx = tanhf(acc[mt][nt][2 * h] * inv);
                    float vy = tanhf(acc[mt][nt][2 * h + 1] * inv);
                    if (OUTF32) {
                        *(float2*)(outf + (size_t)m * N + n) = make_float2(vx, vy);
                    } else {
                        bf162 lo;
                        bf162 hi = split_hi2(vx, vy, lo);
                        size_t oi = act_idx(m, n, N);
                        *(bf162*)(outh + oi) = hi;
                        *(bf162*)(outl + oi) = lo;
                    }
                }
            }
        }
    }
}

// ======================= weight prep (transpose + split + tile/swizzle) ====
struct WMeta { const float* src; long long dst; int ldsrc; int K; int N; int op; };
struct WTable { WMeta m[32]; int count; long long total; };

__global__ void wprep_kernel(WTable tb) {
    long long t = (long long)blockIdx.x * blockDim.x + threadIdx.x;
    if (t >= tb.total) return;
    int d = 0;
    long long local = t;
    for (; d < tb.count; d++) {
        long long sz = (long long)tb.m[d].K * tb.m[d].N;
        if (local < sz) break;
        local -= sz;
    }
    const WMeta& w = tb.m[d];
    int n = (int)(local / w.K);
    int k = (int)(local % w.K);
    float v = w.src[(size_t)k * w.ldsrc + n];
    if (w.op) v = tanhf(v);
    bf16 h = __float2bfloat16(v);
    bf16 l = __float2bfloat16(v - __bfloat162float(h));
    // tiled dst: [n/256][k/64][256][64], SW128-swizzled 128B rows
    long long boff = ((long long)(n >> 8) * (w.K >> 6) + (k >> 6)) * 16384
                   + (sw128(((uint32_t)(n & 255) << 7) + ((uint32_t)(k & 63) << 1)) >> 1);
    g_wh[w.dst + boff] = h;
    g_wl[w.dst + boff] = l;
}

// ======================= attention fold: Wfold = Wv @ Wo, bfold = bv@Wo + bo
__global__ void afold_kernel(const float* __restrict__ awqkv,
                             const float* __restrict__ abqkv,
                             const float* __restrict__ awo,
                             const float* __restrict__ abo,
                             long long dstoff) {
    int i = blockIdx.y;          // 0..1
    int k = blockIdx.x;          // 0..255
    int n = threadIdx.x;         // 0..255
    const float* Wv = awqkv + (size_t)i * 256 * 768 + 512;
    const float* Wo = awo + (size_t)i * 65536;
    float s = 0.f;
    for (int j = 0; j < 256; j++)
        s += Wv[(size_t)k * 768 + j] * Wo[(size_t)j * 256 + n];
    long long boff = (long long)(k >> 6) * 16384
                   + (sw128(((uint32_t)(n & 255) << 7) + ((uint32_t)(k & 63) << 1)) >> 1);
    long long dst = dstoff + (long long)i * 65536 + boff;
    bf16 h = __float2bfloat16(s);
    g_wh[dst] = h;
    g_wl[dst] = __float2bfloat16(s - __bfloat162float(h));
    if (k == 0) {
        float b = abo[i * 256 + n];
        for (int j = 0; j < 256; j++)
            b += abqkv[i * 768 + 512 + j] * Wo[(size_t)j * 256 + n];
        g_bfold[i * 256 + n] = b;
    }
}

// ======================= x split + lin precompute =======================
__global__ void prep2_kernel(const float* __restrict__ x, const float* __restrict__ gp) {
    size_t i = (size_t)blockIdx.x * blockDim.x + threadIdx.x;
    if (i < (size_t)BATCH * 64) {
        int m = (int)(i >> 6);
        int c = (int)(i & 63) * 4;
        float4 v = ((const float4*)x)[i];
        bf162 l0, l1;
        bf162 h0 = split_hi2(v.x, v.y, l0);
        bf162 h1 = split_hi2(v.z, v.w, l1);
        size_t idx = act_idx(m, c, 256);
        *(bf162*)(g_xh + idx)     = h0;
        *(bf162*)(g_xh + idx + 2) = h1;
        *(bf162*)(g_xl + idx)     = l0;
        *(bf162*)(g_xl + idx + 2) = l1;
    }
    if (i < 8 * NQ) {
        const float* p = gp + i * 6;
        g_lin[i] = sinf(p[0]) + cosf(p[1]) + tanhf(p[2]);
    }
}

// ======================= LayerNorm(768) + GELU, hi/lo tiled in/out ====
__global__ __launch_bounds__(256) void lngelu_kernel(const bf16* __restrict__ ih,
                                                     const bf16* __restrict__ il,
                                                     const float* __restrict__ w,
                                                     const float* __restrict__ b,
                                                     bf16* __restrict__ oh,
                                                     bf16* __restrict__ ol) {
    __shared__ float red[8];
    __shared__ float bc;
    const int row = blockIdx.x;
    const int tid = threadIdx.x;

    float v[3];
    size_t ix[3];
#pragma unroll
    for (int e = 0; e < 3; e++) {
        ix[e] = act_idx(row, tid + e * 256, 768);
        v[e] = join2(ih[ix[e]], il[ix[e]]);
    }

    float s = v[0] + v[1] + v[2];
    {
        int lane = tid & 31, wd = tid >> 5;
#pragma unroll
        for (int o = 16; o > 0; o >>= 1) s += __shfl_xor_sync(0xffffffffu, s, o);
        if (lane == 0) red[wd] = s;
        __syncthreads();
        if (tid < 8) {
            float t = red[tid];
#pragma unroll
            for (int o = 4; o > 0; o >>= 1) t += __shfl_xor_sync(0xffu, t, o);
            if (tid == 0) bc = t;
        }
        __syncthreads();
    }
    float mu = bc * (1.f / 768.f);
    __syncthreads();

    float d0 = v[0] - mu, d1 = v[1] - mu, d2 = v[2] - mu;
    float ss = d0 * d0 + d1 * d1 + d2 * d2;
    {
        int lane = tid & 31, wd = tid >> 5;
#pragma unroll
        for (int o = 16; o > 0; o >>= 1) ss += __shfl_xor_sync(0xffffffffu, ss, o);
        if (lane == 0) red[wd] = ss;
        __syncthreads();
        if (tid < 8) {
            float t = red[tid];
#pragma unroll
            for (int o = 4; o > 0; o >>= 1) t += __shfl_xor_sync(0xffu, t, o);
            if (tid == 0) bc = t;
        }
        __syncthreads();
    }
    float inv = rsqrtf(bc * (1.f / 768.f) + 1e-5f);

#pragma unroll
    for (int e = 0; e < 3; e++) {
        int c = tid + e * 256;
        float o = (v[e] - mu) * inv * w[c] + b[c];
        float g = 0.5f * o * (1.f + erff(o * 0.70710678118654752f));
        bf16 hh = __float2bfloat16(g);
        oh[ix[e]] = hh;
        ol[ix[e]] = __float2bfloat16(g - __bfloat162float(hh));
    }
}

// ======================= host =======================
template <int EPI, int MIX, int OUTF32>
static void launchG(const bf16* Ah, const bf16* Al, const bf16* Wh, const bf16* Wl,
                    const float* bias, bf16* outh, bf16* outl, float* outf,
                    const bf16* auxh, const bf16* auxl,
                    const bf16* resh, const bf16* resl,
                    const float* gp, const float* lin, float alpha, int K, int N) {
    cudaFuncSetAttribute(gemm_mma<EPI, MIX, OUTF32>,
                         cudaFuncAttributeMaxDynamicSharedMemorySize, SMEM_BYTES);
    dim3 grid(N / 256, BATCH / 128);
    gemm_mma<EPI, MIX, OUTF32><<<grid, 512, SMEM_BYTES>>>(
        Ah, Al, Wh, Wl, bias, outh, outl, outf, auxh, auxl, resh, resl, gp, lin, alpha, K, N);
}

extern "C" void kernel_launch(void* const* d_in, const int* in_sizes, int n_in,
                              void* d_out, int out_size) {
    const float* x     = (const float*)d_in[0];
    const float* d0w1  = (const float*)d_in[1];
    const float* d0b1  = (const float*)d_in[2];
    const float* lnw   = (const float*)d_in[3];
    const float* lnb   = (const float*)d_in[4];
    const float* d0w2  = (const float*)d_in[5];
    const float* d0b2  = (const float*)d_in[6];
    const float* d1w1  = (const float*)d_in[7];
    const float* d1b1  = (const float*)d_in[8];
    const float* d1w2  = (const float*)d_in[9];
    const float* d1b2  = (const float*)d_in[10];
    const float* awqkv = (const float*)d_in[11];
    const float* abqkv = (const float*)d_in[12];
    const float* awo   = (const float*)d_in[13];
    const float* abo   = (const float*)d_in[14];
    const float* gp    = (const float*)d_in[15];
    const float* ent   = (const float*)d_in[16];
    const float* nlw1  = (const float*)d_in[17];
    const float* nlb1  = (const float*)d_in[18];
    const float* nlw2  = (const float*)d_in[19];
    const float* nlb2  = (const float*)d_in[20];

    float *lin, *bfold;
    bf16 *xh, *xl, *Ah, *Al, *Bh, *Bl, *h0h, *h0l, *hh, *hl, *t2h, *t2l, *t3h, *t3l, *wh, *wl;
    cudaGetSymbolAddress((void**)&lin,   g_lin);
    cudaGetSymbolAddress((void**)&bfold, g_bfold);
    cudaGetSymbolAddress((void**)&xh,    g_xh);
    cudaGetSymbolAddress((void**)&xl,    g_xl);
    cudaGetSymbolAddress((void**)&Ah,    g_Ah);
    cudaGetSymbolAddress((void**)&Al,    g_Al);
    cudaGetSymbolAddress((void**)&Bh,    g_Bh2);
    cudaGetSymbolAddress((void**)&Bl,    g_Bl2);
    cudaGetSymbolAddress((void**)&h0h,   g_h0h);
    cudaGetSymbolAddress((void**)&h0l,   g_h0l);
    cudaGetSymbolAddress((void**)&hh,    g_hh);
    cudaGetSymbolAddress((void**)&hl,    g_hl);
    cudaGetSymbolAddress((void**)&t2h,   g_t2h);
    cudaGetSymbolAddress((void**)&t2l,   g_t2l);
    cudaGetSymbolAddress((void**)&t3h,   g_t3h);
    cudaGetSymbolAddress((void**)&t3l,   g_t3l);
    cudaGetSymbolAddress((void**)&wh,    g_wh);
    cudaGetSymbolAddress((void**)&wl,    g_wl);

    // ---- weight table (dst: tiled [N/256][K/64][256][64], swizzled) ----
    WTable tb;
    long long off = 0;
    int c = 0;
    size_t o_d0w1[3], o_d0w2[3], o_d1w1[3], o_d1w2[3], o_ent[8], o_n1[4], o_n2[4];
    for (int i = 0; i < 3; i++) { o_d0w1[i] = off; tb.m[c++] = {d0w1 + (size_t)i * 256 * 768, off, 768, 256, 768, 0}; off += 256LL * 768; }
    for (int i = 0; i < 3; i++) { o_d0w2[i] = off; tb.m[c++] = {d0w2 + (size_t)i * 768 * 256, off, 256, 768, 256, 0}; off += 768LL * 256; }
    for (int i = 0; i < 3; i++) { o_d1w1[i] = off; tb.m[c++] = {d1w1 + (size_t)i * 256 * 512, off, 512, 256, 512, 0}; off += 256LL * 512; }
    for (int i = 0; i < 3; i++) { o_d1w2[i] = off; tb.m[c++] = {d1w2 + (size_t)i * 512 * 256, off, 256, 512, 256, 0}; off += 512LL * 256; }
    for (int i = 0; i < 8; i++) { o_ent[i]  = off; tb.m[c++] = {ent + (size_t)i * 256 * 256, off, 256, 256, 256, 1}; off += 256LL * 256; }
    for (int i = 0; i < 4; i++) { o_n1[i]   = off; tb.m[c++] = {nlw1 + (size_t)i * 256 * 256, off, 256, 256, 256, 0}; off += 256LL * 256; }
    for (int i = 0; i < 4; i++) { o_n2[i]   = off; tb.m[c++] = {nlw2 + (size_t)i * 256 * 256, off, 256, 256, 256, 0}; off += 256LL * 256; }
    tb.count = c;
    tb.total = off;
    long long o_fold = off;   // + i*65536

    wprep_kernel<<<(unsigned)((off + 255) / 256), 256>>>(tb);
    afold_kernel<<<dim3(256, 2), 256>>>(awqkv, abqkv, awo, abo, o_fold);
    prep2_kernel<<<(BATCH * 64 + 255) / 256, 256>>>(x, gp);

    const bf16* curh = xh;
    const bf16* curl = xl;

    for (int li = 0; li < 8; li++) {
        bf16* nxth = (li & 1) ? Bh : Ah;
        bf16* nxtl = (li & 1) ? Bl : Al;
        float alpha = (li < 4) ? 0.8f : 0.6f;
        int t = li % 3;

        if (t == 0) {
            int i = li / 3;
            launchG<0,0,0>(curh, curl, wh + o_d0w1[i], wl + o_d0w1[i], d0b1 + (size_t)i * 768,
                           h0h, h0l, nullptr, nullptr, nullptr, nullptr, nullptr,
                           nullptr, nullptr, 0.f, 256, 768);
            lngelu_kernel<<<BATCH, 256>>>(h0h, h0l, lnw + (size_t)i * 768, lnb + (size_t)i * 768, hh, hl);
            launchG<0,0,0>(hh, hl, wh + o_d0w2[i], wl + o_d0w2[i], d0b2 + (size_t)i * 256,
                           t2h, t2l, nullptr, nullptr, nullptr, nullptr, nullptr,
                           nullptr, nullptr, 0.f, 768, 256);
        } else if (t == 1) {
            int i = (li - 1) / 3;
            launchG<1,0,0>(curh, curl, wh + o_d1w1[i], wl + o_d1w1[i], d1b1 + (size_t)i * 512,
                           hh, hl, nullptr, nullptr, nullptr, nullptr, nullptr,
                           nullptr, nullptr, 0.f, 256, 512);
            launchG<0,0,0>(hh, hl, wh + o_d1w2[i], wl + o_d1w2[i], d1b2 + (size_t)i * 256,
                           t2h, t2l, nullptr, nullptr, nullptr, nullptr, nullptr,
                           nullptr, nullptr, 0.f, 512, 256);
        } else {
            int i = (li - 2) / 3;
            launchG<0,0,0>(curh, curl, wh + o_fold + (size_t)i * 65536, wl + o_fold + (size_t)i * 65536,
                           bfold + (size_t)i * 256,
                           t2h, t2l, nullptr, nullptr, nullptr, nullptr, nullptr,
                           nullptr, nullptr, 0.f, 256, 256);
        }

        if (!(li & 1)) {
            launchG<3,1,0>(t2h, t2l, wh + o_ent[li], wl + o_ent[li], nullptr,
                           nxth, nxtl, nullptr, t2h, t2l, curh, curl,
                           gp + (size_t)li * 256 * 6, lin + (size_t)li * 256, alpha, 256, 256);
        } else {
            int j = li / 2;
            launchG<3,0,0>(t2h, t2l, wh + o_ent[li], wl + o_ent[li], nullptr,
                           t3h, t3l, nullptr, t2h, t2l, nullptr, nullptr,
                           gp + (size_t)li * 256 * 6, lin + (size_t)li * 256, 0.f, 256, 256);
            launchG<2,0,0>(t3h, t3l, wh + o_n1[j], wl + o_n1[j], nlb1 + (size_t)j * 256,
                           t2h, t2l, nullptr, nullptr, nullptr, nullptr, nullptr,
                           nullptr, nullptr, 0.f, 256, 256);
            if (li == 7) {
                launchG<4,1,1>(t2h, t2l, wh + o_n2[j], wl + o_n2[j], nlb2 + (size_t)j * 256,
                               nullptr, nullptr, (float*)d_out, t3h, t3l, curh, curl,
                               nullptr, nullptr, alpha, 256, 256);
            } else {
                launchG<4,1,0>(t2h, t2l, wh + o_n2[j], wl + o_n2[j], nlb2 + (size_t)j * 256,
                               nxth, nxtl, nullptr, t3h, t3l, curh, curl,
                               nullptr, nullptr, alpha, 256, 256);
            }
        }
        curh = nxth; curl = nxtl;
    }
}

// round 13
// speedup vs baseline: 1.3077x; 1.0479x over previous
#include <cuda_runtime.h>
#include <cuda_bf16.h>
#include <math.h>
#include <stdint.h>

#define BATCH 65536
#define NQ    256

typedef __nv_bfloat16  bf16;
typedef __nv_bfloat162 bf162;

// ======================= scratch (device globals) =======================
__device__ __align__(256) float g_lin  [8 * NQ];
__device__ __align__(256) float g_bfold[2 * NQ];

__device__ __align__(256) bf16 g_xh [BATCH * NQ];
__device__ __align__(256) bf16 g_xl [BATCH * NQ];
__device__ __align__(256) bf16 g_Ah [BATCH * NQ];
__device__ __align__(256) bf16 g_Al [BATCH * NQ];
__device__ __align__(256) bf16 g_Bh2[BATCH * NQ];
__device__ __align__(256) bf16 g_Bl2[BATCH * NQ];
__device__ __align__(256) bf16 g_h0h[BATCH * 768];
__device__ __align__(256) bf16 g_h0l[BATCH * 768];
__device__ __align__(256) bf16 g_hh [BATCH * 768];
__device__ __align__(256) bf16 g_hl [BATCH * 768];
__device__ __align__(256) bf16 g_t2h[BATCH * NQ];
__device__ __align__(256) bf16 g_t2l[BATCH * NQ];
__device__ __align__(256) bf16 g_t3h[BATCH * NQ];
__device__ __align__(256) bf16 g_t3l[BATCH * NQ];

#define WTOT 3276800
__device__ __align__(256) bf16 g_wh[WTOT];
__device__ __align__(256) bf16 g_wl[WTOT];

// ======================= helpers =======================
__device__ __forceinline__ uint32_t smem_u32(const void* p) {
    uint32_t a;
    asm("{ .reg .u64 t; cvta.to.shared.u64 t, %1; cvt.u32.u64 %0, t; }" : "=r"(a) : "l"(p));
    return a;
}
__host__ __device__ __forceinline__ uint32_t sw64(uint32_t o) {
    return o ^ ((o >> 3) & 0x30);
}
// tiled activation layout: [m/128][k/32][128 rows][32 k] bf16, SW64 within 64B rows.
// returns ELEMENT index. K = feature width (multiple of 32).
__device__ __forceinline__ size_t act_idx(int m, int k, int K) {
    uint32_t o = ((uint32_t)(m & 127) << 6) + ((uint32_t)(k & 31) << 1);
    o = sw64(o);
    return ((size_t)(m >> 7) * (K >> 5) + (k >> 5)) * 4096 + (o >> 1);
}

#define CP_BULK(dst, src, bytes, mbar) \
    asm volatile("cp.async.bulk.shared::cluster.global.mbarrier::complete_tx::bytes [%0], [%1], %2, [%3];" \
        :: "r"(dst), "l"(src), "r"(bytes), "r"(mbar) : "memory")

#define MBARRIER_INIT(mbar, cnt) \
    asm volatile("mbarrier.init.shared.b64 [%0], %1;" \
        :: "r"((uint32_t)(mbar)), "r"((uint32_t)(cnt)) : "memory")
#define MBARRIER_EXPECT_TX(mbar, bytes) \
    asm volatile("mbarrier.arrive.expect_tx.shared.b64 _, [%0], %1;" \
        :: "r"((uint32_t)(mbar)), "r"((uint32_t)(bytes)) : "memory")
#define MBARRIER_WAIT_PARITY(mbar, parity) do { \
    uint32_t _mb = (uint32_t)(mbar); \
    uint32_t _pa = (uint32_t)(parity); \
    uint32_t _done; \
    asm volatile("{\n\t.reg .pred p;\n\tmbarrier.try_wait.parity.acquire.cta.shared::cta.b64 p, [%1], %2;\n\tselp.b32 %0, 1, 0, p;\n\t}" \
        : "=r"(_done) : "r"(_mb), "r"(_pa) : "memory"); \
    if (!_done) { \
        asm volatile("{\n\t.reg .pred P1;\n\tWAIT_LOOP_%=:\n\tmbarrier.try_wait.parity.acquire.cta.shared::cta.b64 P1, [%0], %1, 0x989680;\n\t@P1 bra.uni WAIT_DONE_%=;\n\tbra.uni WAIT_LOOP_%=;\n\tWAIT_DONE_%=:\n\t}" \
            :: "r"(_mb), "r"(_pa) : "memory"); \
    } \
} while (0)

#define LDSM4(r0, r1, r2, r3, addr) \
    asm volatile("ldmatrix.sync.aligned.m8n8.x4.shared.b16 {%0,%1,%2,%3}, [%4];" \
        : "=r"(r0), "=r"(r1), "=r"(r2), "=r"(r3) : "r"(addr))

__device__ __forceinline__ void mma_bf16(float* d, const uint32_t* a, const uint32_t* b) {
    asm volatile(
        "mma.sync.aligned.m16n8k16.row.col.f32.bf16.bf16.f32 "
        "{%0,%1,%2,%3}, {%4,%5,%6,%7}, {%8,%9}, {%0,%1,%2,%3};"
        : "+f"(d[0]), "+f"(d[1]), "+f"(d[2]), "+f"(d[3])
        : "r"(a[0]), "r"(a[1]), "r"(a[2]), "r"(a[3]), "r"(b[0]), "r"(b[1]));
}

__device__ __forceinline__ bf162 split_hi2(float a, float b, bf162& lo) {
    bf16 ha = __float2bfloat16(a);
    bf16 hb = __float2bfloat16(b);
    bf16 la = __float2bfloat16(a - __bfloat162float(ha));
    bf16 lb = __float2bfloat16(b - __bfloat162float(hb));
    lo = __halves2bfloat162(la, lb);
    return __halves2bfloat162(ha, hb);
}
__device__ __forceinline__ float join2(bf16 h, bf16 l) {
    return __bfloat162float(h) + __bfloat162float(l);
}

// ======================= smem layout (tile 128 M x 256 N, k-chunk 32) ====
// Stage: Ah 8K | Al 8K | Bh 16K | Bl 16K = 48 KB. 4 stages + barriers.
#define ST_AL 8192
#define ST_BH 16384
#define ST_BL 32768
#define STAGE_BYTES 49152
#define NSTAGES 4
#define MB_OFF (NSTAGES * STAGE_BYTES)
#define SMEM_BYTES (NSTAGES * STAGE_BYTES + 32)

// ======================= bulk-TMA mma.sync GEMM =======================
// A planes tiled [B/128][K/32][128][32] (SW64); W planes tiled [N/256][K/32][256][32].
// EPI: 0 bias, 1 silu, 2 tanh, 3 gate+entangle, 4 nl-residual
// MIX: fused alpha-mix + row L2-normalize + tanh; OUTF32: mix writes f32 linear (d_out)
template <int EPI, int MIX, int OUTF32>
__global__ __launch_bounds__(512, 1) void gemm_mma(
    const bf16* __restrict__ Ah, const bf16* __restrict__ Al,
    const bf16* __restrict__ Bh, const bf16* __restrict__ Bl,
    const float* __restrict__ bias,
    bf16* __restrict__ outh, bf16* __restrict__ outl, float* __restrict__ outf,
    const bf16* __restrict__ auxh, const bf16* __restrict__ auxl,
    const bf16* __restrict__ resh, const bf16* __restrict__ resl,
    const float* __restrict__ gp, const float* __restrict__ lin,
    float alpha, int K, int N)
{
    extern __shared__ char sm[];
    const uint32_t smem_base = smem_u32(sm);

    const int tid    = threadIdx.x;
    const int wid    = tid >> 5;
    const int lane   = tid & 31;
    const int warp_m = wid & 3;        // 4 warps over M: 32 rows each
    const int warp_n = wid >> 2;       // 4 warps over N: 64 cols each
    const int blkm   = blockIdx.y;
    const int blkn   = blockIdx.x;
    const int m0     = blkm * 128;
    const int n0     = blkn * 256;
    const int nc     = K >> 5;

    float acc[2][8][4];
#pragma unroll
    for (int a = 0; a < 2; a++)
#pragma unroll
        for (int b = 0; b < 8; b++)
#pragma unroll
            for (int c = 0; c < 4; c++) acc[a][b][c] = 0.f;

    auto issue = [&](int s, int c) {
        uint32_t sb = smem_base + s * STAGE_BYTES;
        uint32_t mb = smem_base + MB_OFF + s * 8;
        MBARRIER_EXPECT_TX(mb, 49152);
        CP_BULK(sb,           Ah + ((size_t)blkm * nc + c) * 4096, 8192,  mb);
        CP_BULK(sb + ST_AL,   Al + ((size_t)blkm * nc + c) * 4096, 8192,  mb);
        CP_BULK(sb + ST_BH,   Bh + ((size_t)blkn * nc + c) * 8192, 16384, mb);
        CP_BULK(sb + ST_BL,   Bl + ((size_t)blkn * nc + c) * 8192, 16384, mb);
    };

    if (tid == 0) {
#pragma unroll
        for (int s = 0; s < NSTAGES; s++) MBARRIER_INIT(smem_base + MB_OFF + s * 8, 1);
    }
    __syncthreads();
    if (tid == 0) {
#pragma unroll
        for (int s = 0; s < NSTAGES; s++) issue(s, s);   // nc >= 8 always
    }

    // per-lane base offsets (pre-swizzle byte offsets within a 64B-pitch plane)
    const uint32_t oA0 = (((uint32_t)(warp_m * 32 + (lane & 15))) << 6) + ((lane >> 4) << 4);
    const uint32_t oB0 = (((uint32_t)(warp_n * 64 + (lane & 7) + ((lane >> 4) << 3))) << 6)
                       + (((lane >> 3) & 1) << 4);

    for (int i = 0; i < nc; i++) {
        const int s = i & 3;
        MBARRIER_WAIT_PARITY(smem_base + MB_OFF + s * 8, (i >> 2) & 1);

        const uint32_t sb = smem_base + s * STAGE_BYTES;
#pragma unroll
        for (int kk = 0; kk < 2; kk++) {
            const uint32_t ko = kk << 5;     // 16 k = 32 bytes
            uint32_t af_h[2][4], af_l[2][4];
#pragma unroll
            for (int mt = 0; mt < 2; mt++) {
                uint32_t o = oA0 + (mt << 10) + ko;   // mt*16 rows * 64B
                o = sw64(o);
                LDSM4(af_h[mt][0], af_h[mt][1], af_h[mt][2], af_h[mt][3], sb + o);
                LDSM4(af_l[mt][0], af_l[mt][1], af_l[mt][2], af_l[mt][3], sb + ST_AL + o);
            }
#pragma unroll
            for (int p = 0; p < 4; p++) {
                uint32_t o = oB0 + (p << 10) + ko;
                o = sw64(o);
                uint32_t bh[2][2], bl[2][2];
                LDSM4(bh[0][0], bh[0][1], bh[1][0], bh[1][1], sb + ST_BH + o);
                LDSM4(bl[0][0], bl[0][1], bl[1][0], bl[1][1], sb + ST_BL + o);
#pragma unroll
                for (int mt = 0; mt < 2; mt++)
#pragma unroll
                    for (int q = 0; q < 2; q++) {
                        const int nt = p * 2 + q;
                        mma_bf16(acc[mt][nt], af_h[mt], bh[q]);
                        mma_bf16(acc[mt][nt], af_l[mt], bh[q]);
                        mma_bf16(acc[mt][nt], af_h[mt], bl[q]);
                    }
            }
        }
        __syncthreads();
        if (i + NSTAGES < nc && tid == 0) issue(s, i + NSTAGES);
    }

    // ---------- epilogue ----------
    float* red = (float*)sm;                 // [128 rows][4 warp_n] (stage smem reused)

    const int l4  = lane >> 2;
    const int l2q = lane & 3;
    const int l2  = l2q * 2;
    const float beta = 1.f - alpha;

#pragma unroll
    for (int mt = 0; mt < 2; mt++) {
#pragma unroll
        for (int h = 0; h < 2; h++) {
            const int mrow = warp_m * 32 + mt * 16 + h * 8 + l4;
            const int m = m0 + mrow;
            float part = 0.f;
#pragma unroll
            for (int nt = 0; nt < 8; nt++) {
                const int n = n0 + warp_n * 64 + nt * 8 + l2;
                float vx = acc[mt][nt][2 * h];
                float vy = acc[mt][nt][2 * h + 1];

                if (EPI != 3) {
                    float2 b2 = *(const float2*)(bias + n);
                    vx += b2.x; vy += b2.y;
                }
                if (EPI == 1) {
                    vx = vx / (1.f + expf(-vx));
                    vy = vy / (1.f + expf(-vy));
                } else if (EPI == 2) {
                    vx = tanhf(vx);
                    vy = tanhf(vy);
                } else if (EPI == 3) {
                    size_t ai = act_idx(m, n, N);
                    bf162 axh = *(const bf162*)(auxh + ai);
                    bf162 axl = *(const bf162*)(auxl + ai);
                    float c0 = join2(axh.x, axl.x);
                    float c1 = join2(axh.y, axl.y);
                    float li0 = __ldg(lin + n),     li1 = __ldg(lin + n + 1);
                    float p30 = __ldg(gp + (size_t)n * 6 + 3), p31 = __ldg(gp + (size_t)(n + 1) * 6 + 3);
                    float p40 = __ldg(gp + (size_t)n * 6 + 4), p41 = __ldg(gp + (size_t)(n + 1) * 6 + 4);
                    float p50 = __ldg(gp + (size_t)n * 6 + 5), p51 = __ldg(gp + (size_t)(n + 1) * 6 + 5);
                    float g0 = 0.25f * (li0 * c0 + 0.5f * sinf(p30 * c0 + p40) + 0.5f * cosf(p50 * c0));
                    float g1 = 0.25f * (li1 * c1 + 0.5f * sinf(p31 * c1 + p41) + 0.5f * cosf(p51 * c1));
                    vx = (c0 + 0.3f * g0 + 0.2f * vx) * (1.f / 1.5f);
                    vy = (c1 + 0.3f * g1 + 0.2f * vy) * (1.f / 1.5f);
                } else if (EPI == 4) {
                    size_t ai = act_idx(m, n, N);
                    bf162 axh = *(const bf162*)(auxh + ai);
                    bf162 axl = *(const bf162*)(auxl + ai);
                    vx = join2(axh.x, axl.x) + 0.1f * vx;
                    vy = join2(axh.y, axl.y) + 0.1f * vy;
                }

                if (MIX) {
                    size_t ri = act_idx(m, n, N);
                    bf162 rh = *(const bf162*)(resh + ri);
                    bf162 rl = *(const bf162*)(resl + ri);
                    vx = alpha * vx + beta * join2(rh.x, rl.x);
                    vy = alpha * vy + beta * join2(rh.y, rl.y);
                    part += vx * vx + vy * vy;
                    acc[mt][nt][2 * h]     = vx;
                    acc[mt][nt][2 * h + 1] = vy;
                } else {
                    bf162 lo;
                    bf162 hi = split_hi2(vx, vy, lo);
                    size_t oi = act_idx(m, n, N);
                    *(bf162*)(outh + oi) = hi;
                    *(bf162*)(outl + oi) = lo;
                }
            }
            if (MIX) {
                part += __shfl_xor_sync(0xffffffffu, part, 1);
                part += __shfl_xor_sync(0xffffffffu, part, 2);
                if (l2q == 0) red[mrow * 4 + warp_n] = part;
            }
        }
    }

    if (MIX) {
        __syncthreads();
#pragma unroll
        for (int mt = 0; mt < 2; mt++) {
#pragma unroll
            for (int h = 0; h < 2; h++) {
                const int mrow = warp_m * 32 + mt * 16 + h * 8 + l4;
                const int m = m0 + mrow;
                float ss = red[mrow * 4] + red[mrow * 4 + 1] + red[mrow * 4 + 2] + red[mrow * 4 + 3];
                float inv = 1.f / (sqrtf(ss) + 1e-8f);
#pragma unroll
                for (int nt = 0; nt < 8; nt++) {
                    const int n = n0 + warp_n * 64 + nt * 8 + l2;
                    float vx = tanhf(acc[mt][nt][2 * h] * inv);
                    float vy = tanhf(acc[mt][nt][2 * h + 1] * inv);
                    if (OUTF32) {
                        *(float2*)(outf + (size_t)m * N + n) = make_float2(vx, vy);
                    } else {
                        bf162 lo;
                        bf162 hi = split_hi2(vx, vy, lo);
                        size_t oi = act_idx(m, n, N);
                        *(bf162*)(outh + oi) = hi;
                        *(bf162*)(outl + oi) = lo;
                    }
                }
            }
        }
    }
}

// ======================= weight prep (transpose + split + tile/swizzle) ====
struct WMeta { const float* src; long long dst; int ldsrc; int K; int N; int op; };
struct WTable { WMeta m[32]; int count; long long total; };

__global__ void wprep_kernel(WTable tb) {
    long long t = (long long)blockIdx.x * blockDim.x + threadIdx.x;
    if (t >= tb.total) return;
    int d = 0;
    long long local = t;
    for (; d < tb.count; d++) {
        long long sz = (long long)tb.m[d].K * tb.m[d].N;
        if (local < sz) break;
        local -= sz;
    }
    const WMeta& w = tb.m[d];
    int n = (int)(local / w.K);
    int k = (int)(local % w.K);
    float v = w.src[(size_t)k * w.ldsrc + n];
    if (w.op) v = tanhf(v);
    bf16 h = __float2bfloat16(v);
    bf16 l = __float2bfloat16(v - __bfloat162float(h));
    // tiled dst: [n/256][k/32][256][32], SW64-swizzled 64B rows
    long long boff = ((long long)(n >> 8) * (w.K >> 5) + (k >> 5)) * 8192
                   + (sw64(((uint32_t)(n & 255) << 6) + ((uint32_t)(k & 31) << 1)) >> 1);
    g_wh[w.dst + boff] = h;
    g_wl[w.dst + boff] = l;
}

// ======================= attention fold: Wfold = Wv @ Wo, bfold = bv@Wo + bo
__global__ void afold_kernel(const float* __restrict__ awqkv,
                             const float* __restrict__ abqkv,
                             const float* __restrict__ awo,
                             const float* __restrict__ abo,
                             long long dstoff) {
    int i = blockIdx.y;          // 0..1
    int k = blockIdx.x;          // 0..255
    int n = threadIdx.x;         // 0..255
    const float* Wv = awqkv + (size_t)i * 256 * 768 + 512;
    const float* Wo = awo + (size_t)i * 65536;
    float s = 0.f;
    for (int j = 0; j < 256; j++)
        s += Wv[(size_t)k * 768 + j] * Wo[(size_t)j * 256 + n];
    long long boff = (long long)(k >> 5) * 8192
                   + (sw64(((uint32_t)n << 6) + ((uint32_t)(k & 31) << 1)) >> 1);
    long long dst = dstoff + (long long)i * 65536 + boff;
    bf16 h = __float2bfloat16(s);
    g_wh[dst] = h;
    g_wl[dst] = __float2bfloat16(s - __bfloat162float(h));
    if (k == 0) {
        float b = abo[i * 256 + n];
        for (int j = 0; j < 256; j++)
            b += abqkv[i * 768 + 512 + j] * Wo[(size_t)j * 256 + n];
        g_bfold[i * 256 + n] = b;
    }
}

// ======================= x split + lin precompute =======================
__global__ void prep2_kernel(const float* __restrict__ x, const float* __restrict__ gp) {
    size_t i = (size_t)blockIdx.x * blockDim.x + threadIdx.x;
    if (i < (size_t)BATCH * 64) {
        int m = (int)(i >> 6);
        int c = (int)(i & 63) * 4;
        float4 v = ((const float4*)x)[i];
        bf162 l0, l1;
        bf162 h0 = split_hi2(v.x, v.y, l0);
        bf162 h1 = split_hi2(v.z, v.w, l1);
        size_t idx = act_idx(m, c, 256);
        *(bf162*)(g_xh + idx)     = h0;
        *(bf162*)(g_xh + idx + 2) = h1;
        *(bf162*)(g_xl + idx)     = l0;
        *(bf162*)(g_xl + idx + 2) = l1;
    }
    if (i < 8 * NQ) {
        const float* p = gp + i * 6;
        g_lin[i] = sinf(p[0]) + cosf(p[1]) + tanhf(p[2]);
    }
}

// ======================= LayerNorm(768) + GELU, hi/lo tiled in/out ====
__global__ __launch_bounds__(256) void lngelu_kernel(const bf16* __restrict__ ih,
                                                     const bf16* __restrict__ il,
                                                     const float* __restrict__ w,
                                                     const float* __restrict__ b,
                                                     bf16* __restrict__ oh,
                                                     bf16* __restrict__ ol) {
    __shared__ float red[8];
    __shared__ float bc;
    const int row = blockIdx.x;
    const int tid = threadIdx.x;

    float v[3];
    size_t ix[3];
#pragma unroll
    for (int e = 0; e < 3; e++) {
        ix[e] = act_idx(row, tid + e * 256, 768);
        v[e] = join2(ih[ix[e]], il[ix[e]]);
    }

    float s = v[0] + v[1] + v[2];
    {
        int lane = tid & 31, wd = tid >> 5;
#pragma unroll
        for (int o = 16; o > 0; o >>= 1) s += __shfl_xor_sync(0xffffffffu, s, o);
        if (lane == 0) red[wd] = s;
        __syncthreads();
        if (tid < 8) {
            float t = red[tid];
#pragma unroll
            for (int o = 4; o > 0; o >>= 1) t += __shfl_xor_sync(0xffu, t, o);
            if (tid == 0) bc = t;
        }
        __syncthreads();
    }
    float mu = bc * (1.f / 768.f);
    __syncthreads();

    float d0 = v[0] - mu, d1 = v[1] - mu, d2 = v[2] - mu;
    float ss = d0 * d0 + d1 * d1 + d2 * d2;
    {
        int lane = tid & 31, wd = tid >> 5;
#pragma unroll
        for (int o = 16; o > 0; o >>= 1) ss += __shfl_xor_sync(0xffffffffu, ss, o);
        if (lane == 0) red[wd] = ss;
        __syncthreads();
        if (tid < 8) {
            float t = red[tid];
#pragma unroll
            for (int o = 4; o > 0; o >>= 1) t += __shfl_xor_sync(0xffu, t, o);
            if (tid == 0) bc = t;
        }
        __syncthreads();
    }
    float inv = rsqrtf(bc * (1.f / 768.f) + 1e-5f);

#pragma unroll
    for (int e = 0; e < 3; e++) {
        int c = tid + e * 256;
        float o = (v[e] - mu) * inv * w[c] + b[c];
        float g = 0.5f * o * (1.f + erff(o * 0.70710678118654752f));
        bf16 hh = __float2bfloat16(g);
        oh[ix[e]] = hh;
        ol[ix[e]] = __float2bfloat16(g - __bfloat162float(hh));
    }
}

// ======================= host =======================
template <int EPI, int MIX, int OUTF32>
static void launchG(const bf16* Ah, const bf16* Al, const bf16* Wh, const bf16* Wl,
                    const float* bias, bf16* outh, bf16* outl, float* outf,
                    const bf16* auxh, const bf16* auxl,
                    const bf16* resh, const bf16* resl,
                    const float* gp, const float* lin, float alpha, int K, int N) {
    cudaFuncSetAttribute(gemm_mma<EPI, MIX, OUTF32>,
                         cudaFuncAttributeMaxDynamicSharedMemorySize, SMEM_BYTES);
    dim3 grid(N / 256, BATCH / 128);
    gemm_mma<EPI, MIX, OUTF32><<<grid, 512, SMEM_BYTES>>>(
        Ah, Al, Wh, Wl, bias, outh, outl, outf, auxh, auxl, resh, resl, gp, lin, alpha, K, N);
}

extern "C" void kernel_launch(void* const* d_in, const int* in_sizes, int n_in,
                              void* d_out, int out_size) {
    const float* x     = (const float*)d_in[0];
    const float* d0w1  = (const float*)d_in[1];
    const float* d0b1  = (const float*)d_in[2];
    const float* lnw   = (const float*)d_in[3];
    const float* lnb   = (const float*)d_in[4];
    const float* d0w2  = (const float*)d_in[5];
    const float* d0b2  = (const float*)d_in[6];
    const float* d1w1  = (const float*)d_in[7];
    const float* d1b1  = (const float*)d_in[8];
    const float* d1w2  = (const float*)d_in[9];
    const float* d1b2  = (const float*)d_in[10];
    const float* awqkv = (const float*)d_in[11];
    const float* abqkv = (const float*)d_in[12];
    const float* awo   = (const float*)d_in[13];
    const float* abo   = (const float*)d_in[14];
    const float* gp    = (const float*)d_in[15];
    const float* ent   = (const float*)d_in[16];
    const float* nlw1  = (const float*)d_in[17];
    const float* nlb1  = (const float*)d_in[18];
    const float* nlw2  = (const float*)d_in[19];
    const float* nlb2  = (const float*)d_in[20];

    float *lin, *bfold;
    bf16 *xh, *xl, *Ah, *Al, *Bh, *Bl, *h0h, *h0l, *hh, *hl, *t2h, *t2l, *t3h, *t3l, *wh, *wl;
    cudaGetSymbolAddress((void**)&lin,   g_lin);
    cudaGetSymbolAddress((void**)&bfold, g_bfold);
    cudaGetSymbolAddress((void**)&xh,    g_xh);
    cudaGetSymbolAddress((void**)&xl,    g_xl);
    cudaGetSymbolAddress((void**)&Ah,    g_Ah);
    cudaGetSymbolAddress((void**)&Al,    g_Al);
    cudaGetSymbolAddress((void**)&Bh,    g_Bh2);
    cudaGetSymbolAddress((void**)&Bl,    g_Bl2);
    cudaGetSymbolAddress((void**)&h0h,   g_h0h);
    cudaGetSymbolAddress((void**)&h0l,   g_h0l);
    cudaGetSymbolAddress((void**)&hh,    g_hh);
    cudaGetSymbolAddress((void**)&hl,    g_hl);
    cudaGetSymbolAddress((void**)&t2h,   g_t2h);
    cudaGetSymbolAddress((void**)&t2l,   g_t2l);
    cudaGetSymbolAddress((void**)&t3h,   g_t3h);
    cudaGetSymbolAddress((void**)&t3l,   g_t3l);
    cudaGetSymbolAddress((void**)&wh,    g_wh);
    cudaGetSymbolAddress((void**)&wl,    g_wl);

    // ---- weight table (dst: tiled [N/256][K/32][256][32], SW64) ----
    WTable tb;
    long long off = 0;
    int c = 0;
    size_t o_d0w1[3], o_d0w2[3], o_d1w1[3], o_d1w2[3], o_ent[8], o_n1[4], o_n2[4];
    for (int i = 0; i < 3; i++) { o_d0w1[i] = off; tb.m[c++] = {d0w1 + (size_t)i * 256 * 768, off, 768, 256, 768, 0}; off += 256LL * 768; }
    for (int i = 0; i < 3; i++) { o_d0w2[i] = off; tb.m[c++] = {d0w2 + (size_t)i * 768 * 256, off, 256, 768, 256, 0}; off += 768LL * 256; }
    for (int i = 0; i < 3; i++) { o_d1w1[i] = off; tb.m[c++] = {d1w1 + (size_t)i * 256 * 512, off, 512, 256, 512, 0}; off += 256LL * 512; }
    for (int i = 0; i < 3; i++) { o_d1w2[i] = off; tb.m[c++] = {d1w2 + (size_t)i * 512 * 256, off, 256, 512, 256, 0}; off += 512LL * 256; }
    for (int i = 0; i < 8; i++) { o_ent[i]  = off; tb.m[c++] = {ent + (size_t)i * 256 * 256, off, 256, 256, 256, 1}; off += 256LL * 256; }
    for (int i = 0; i < 4; i++) { o_n1[i]   = off; tb.m[c++] = {nlw1 + (size_t)i * 256 * 256, off, 256, 256, 256, 0}; off += 256LL * 256; }
    for (int i = 0; i < 4; i++) { o_n2[i]   = off; tb.m[c++] = {nlw2 + (size_t)i * 256 * 256, off, 256, 256, 256, 0}; off += 256LL * 256; }
    tb.count = c;
    tb.total = off;
    long long o_fold = off;   // + i*65536

    wprep_kernel<<<(unsigned)((off + 255) / 256), 256>>>(tb);
    afold_kernel<<<dim3(256, 2), 256>>>(awqkv, abqkv, awo, abo, o_fold);
    prep2_kernel<<<(BATCH * 64 + 255) / 256, 256>>>(x, gp);

    const bf16* curh = xh;
    const bf16* curl = xl;

    for (int li = 0; li < 8; li++) {
        bf16* nxth = (li & 1) ? Bh : Ah;
        bf16* nxtl = (li & 1) ? Bl : Al;
        float alpha = (li < 4) ? 0.8f : 0.6f;
        int t = li % 3;

        if (t == 0) {
            int i = li / 3;
            launchG<0,0,0>(curh, curl, wh + o_d0w1[i], wl + o_d0w1[i], d0b1 + (size_t)i * 768,
                           h0h, h0l, nullptr, nullptr, nullptr, nullptr, nullptr,
                           nullptr, nullptr, 0.f, 256, 768);
            lngelu_kernel<<<BATCH, 256>>>(h0h, h0l, lnw + (size_t)i * 768, lnb + (size_t)i * 768, hh, hl);
            launchG<0,0,0>(hh, hl, wh + o_d0w2[i], wl + o_d0w2[i], d0b2 + (size_t)i * 256,
                           t2h, t2l, nullptr, nullptr, nullptr, nullptr, nullptr,
                           nullptr, nullptr, 0.f, 768, 256);
        } else if (t == 1) {
            int i = (li - 1) / 3;
            launchG<1,0,0>(curh, curl, wh + o_d1w1[i], wl + o_d1w1[i], d1b1 + (size_t)i * 512,
                           hh, hl, nullptr, nullptr, nullptr, nullptr, nullptr,
                           nullptr, nullptr, 0.f, 256, 512);
            launchG<0,0,0>(hh, hl, wh + o_d1w2[i], wl + o_d1w2[i], d1b2 + (size_t)i * 256,
                           t2h, t2l, nullptr, nullptr, nullptr, nullptr, nullptr,
                           nullptr, nullptr, 0.f, 512, 256);
        } else {
            int i = (li - 2) / 3;
            launchG<0,0,0>(curh, curl, wh + o_fold + (size_t)i * 65536, wl + o_fold + (size_t)i * 65536,
                           bfold + (size_t)i * 256,
                           t2h, t2l, nullptr, nullptr, nullptr, nullptr, nullptr,
                           nullptr, nullptr, 0.f, 256, 256);
        }

        if (!(li & 1)) {
            launchG<3,1,0>(t2h, t2l, wh + o_ent[li], wl + o_ent[li], nullptr,
                           nxth, nxtl, nullptr, t2h, t2l, curh, curl,
                           gp + (size_t)li * 256 * 6, lin + (size_t)li * 256, alpha, 256, 256);
        } else {
            int j = li / 2;
            launchG<3,0,0>(t2h, t2l, wh + o_ent[li], wl + o_ent[li], nullptr,
                           t3h, t3l, nullptr, t2h, t2l, nullptr, nullptr,
                           gp + (size_t)li * 256 * 6, lin + (size_t)li * 256, 0.f, 256, 256);
            launchG<2,0,0>(t3h, t3l, wh + o_n1[j], wl + o_n1[j], nlb1 + (size_t)j * 256,
                           t2h, t2l, nullptr, nullptr, nullptr, nullptr, nullptr,
                           nullptr, nullptr, 0.f, 256, 256);
            if (li == 7) {
                launchG<4,1,1>(t2h, t2l, wh + o_n2[j], wl + o_n2[j], nlb2 + (size_t)j * 256,
                               nullptr, nullptr, (float*)d_out, t3h, t3l, curh, curl,
                               nullptr, nullptr, alpha, 256, 256);
            } else {
                launchG<4,1,0>(t2h, t2l, wh + o_n2[j], wl + o_n2[j], nlb2 + (size_t)j * 256,
                               nxth, nxtl, nullptr, t3h, t3l, curh, curl,
                               nullptr, nullptr, alpha, 256, 256);
            }
        }
        curh = nxth; curl = nxtl;
    }
}